// round 2
// baseline (speedup 1.0000x reference)
#include <cuda_runtime.h>
#include <cstdint>
#include <cstddef>

#define BB 16
#define NN 458
#define DD 128
#define EE 42240

// ---------------------------------------------------------------------------
// Scratch (device globals; no allocation allowed)
// ---------------------------------------------------------------------------
__device__ float g_x  [BB * NN * DD];        // current node features (after layer update)
__device__ float g_u  [BB * NN * DD];        // x @ W_src
__device__ float g_v  [BB * NN * DD];        // x @ W_dst + b_msg
__device__ float g_agg[2 * BB * NN * DD];    // two partial agg buffers (s-split halves)

// ---------------------------------------------------------------------------
// uv kernel: u = x @ Wsrc ; v = x @ Wdst + b_msg     (rows = B*N, 16 rows/CTA)
// wl points at w_msg[l] (shape [384,128] row-major). Wsrc = rows 0..127,
// Wdst = rows 128..255.
// ---------------------------------------------------------------------------
__global__ __launch_bounds__(128) void uv_kernel(const float* __restrict__ xin,
                                                 const float* __restrict__ wl,
                                                 const float* __restrict__ bl)
{
    __shared__ float xs[16][128];
    const int t    = threadIdx.x;
    const int row0 = blockIdx.x * 16;

    // pick input: explicit pointer (layer 0) or g_x (later layers)
    const float* x = (xin != nullptr) ? xin : g_x;

    // load 16 rows of x into smem (float4, coalesced)
    {
        const float4* src = (const float4*)(x + (size_t)row0 * DD);
        float4* dst = (float4*)&xs[0][0];
        #pragma unroll
        for (int i = 0; i < 4; i++) dst[t + i * 128] = src[t + i * 128];
    }
    __syncthreads();

    float au[16], av[16];
    #pragma unroll
    for (int r = 0; r < 16; r++) { au[r] = 0.f; av[r] = 0.f; }

    #pragma unroll 4
    for (int k = 0; k < 128; k++) {
        const float wu = __ldg(wl + k * 128 + t);
        const float wv = __ldg(wl + (128 + k) * 128 + t);
        #pragma unroll
        for (int r = 0; r < 16; r++) {
            const float xv = xs[r][k];
            au[r] += xv * wu;
            av[r] += xv * wv;
        }
    }

    const float bias = bl[t];
    #pragma unroll
    for (int r = 0; r < 16; r++) {
        const size_t o = (size_t)(row0 + r) * DD + t;
        g_u[o] = au[r];
        g_v[o] = av[r] + bias;
    }
}

// ---------------------------------------------------------------------------
// edge kernel: for each (batch, bipartite block, 32-dst tile, s-half):
//   agg[d,:] += (1/n_src) * sum_s relu( (e(s,d) @ Wedge) + u[s] + v[d] )
// Fused GEMM + aggregation, Wedge (64KB) + V tile (16KB) resident in smem,
// edge tiles (2 src x 32 dst = 64 rows x 128) staged through smem.
// Grid = 16 batches * 2 splits * 13 tiles = 416 CTAs, 256 threads.
// ---------------------------------------------------------------------------
#define EDGE_SMEM_FLOATS (16384 + 4096 + 64 * 132 + 256)

__global__ __launch_bounds__(256) void edge_kernel(const float* __restrict__ edge_attr,
                                                   const float* __restrict__ wl)
{
    extern __shared__ float sm[];
    float* sW = sm;                 // [128][128] Wedge
    float* sV = sm + 16384;         // [32][128]  v rows for dst tile
    float* sA = sm + 16384 + 4096;  // [64][132]  edge tile (padded)
    float* sU = sA + 64 * 132;      // [2][128]   u rows for src chunk

    const int tid = threadIdx.x;
    const int bx  = blockIdx.x;
    const int b     = bx / 26;
    const int rem   = bx % 26;
    const int split = rem / 13;
    const int tt    = rem % 13;

    int lb, dtile;
    if      (tt < 4)  { lb = 0; dtile = tt;      }
    else if (tt < 8)  { lb = 1; dtile = tt - 4;  }
    else if (tt < 12) { lb = 2; dtile = tt - 8;  }
    else              { lb = 3; dtile = 0;       }

    const int nsrc_a[4] = {64, 128, 128, 128};
    const int ndst_a[4] = {128, 128, 128, 10};
    const int eb_a  [4] = {0, 8192, 24576, 40960};
    const int so_a  [4] = {0, 64, 192, 320};
    const int do_a  [4] = {64, 192, 320, 448};

    const int n_src = nsrc_a[lb];
    const int n_dst = ndst_a[lb];
    const int ebase = eb_a[lb];
    const int soff  = so_a[lb];
    const int doff  = do_a[lb];
    const int d0    = dtile * 32;

    const int s_begin = split * (n_src >> 1);
    const int s_end   = s_begin + (n_src >> 1);

    // --- load Wedge (rows 256..383 of w_msg[l]) into smem ---
    {
        const float4* wsrc = (const float4*)(wl + 256 * 128);
        float4* d4 = (float4*)sW;
        #pragma unroll
        for (int i = tid; i < 4096; i += 256) d4[i] = wsrc[i];
    }
    // --- load V tile into smem (0-fill masked dst) ---
    for (int i = tid; i < 4096; i += 256) {
        const int dl = i >> 7, c = i & 127;
        const int dg = d0 + dl;
        sV[i] = (dg < n_dst) ? g_v[((size_t)b * NN + doff + dg) * DD + c] : 0.f;
    }

    const int trow = tid >> 4;   // 0..15  -> dst pair (trow*2 + {0,1})
    const int tcol = tid & 15;   // 0..15  -> cols tcol*8 .. tcol*8+7
    const int col  = tcol * 8;

    float agg[2][8];
    #pragma unroll
    for (int d = 0; d < 2; d++)
        #pragma unroll
        for (int j = 0; j < 8; j++) agg[d][j] = 0.f;

    for (int s0 = s_begin; s0 < s_end; s0 += 2) {
        __syncthreads();   // previous iteration done reading sA/sU

        // stage edge tile: 64 rows (2 src x 32 dst) x 128 floats
        for (int i = tid; i < 2048; i += 256) {
            const int r  = i >> 5, c4 = i & 31;
            const int sl = r >> 5, dl = r & 31;
            const int dg = d0 + dl;
            float4 v4 = make_float4(0.f, 0.f, 0.f, 0.f);
            if (dg < n_dst) {
                const size_t e = (size_t)ebase + (size_t)(s0 + sl) * n_dst + dg;
                v4 = *(const float4*)(edge_attr + ((size_t)b * EE + e) * DD + c4 * 4);
            }
            *(float4*)(sA + r * 132 + c4 * 4) = v4;
        }
        // stage u rows for the 2 src
        {
            const int sl = tid >> 7, c = tid & 127;
            sU[tid] = g_u[((size_t)b * NN + soff + s0 + sl) * DD + c];
        }
        __syncthreads();

        float acc[2][2][8];
        #pragma unroll
        for (int s = 0; s < 2; s++)
            #pragma unroll
            for (int d = 0; d < 2; d++)
                #pragma unroll
                for (int j = 0; j < 8; j++) acc[s][d][j] = 0.f;

        #pragma unroll 2
        for (int k = 0; k < 128; k++) {
            const float4 b0 = *(const float4*)(sW + k * 128 + col);
            const float4 b1 = *(const float4*)(sW + k * 128 + col + 4);
            const float bv[8] = {b0.x, b0.y, b0.z, b0.w, b1.x, b1.y, b1.z, b1.w};
            float av[2][2];
            #pragma unroll
            for (int s = 0; s < 2; s++)
                #pragma unroll
                for (int d = 0; d < 2; d++)
                    av[s][d] = sA[(s * 32 + trow * 2 + d) * 132 + k];
            #pragma unroll
            for (int s = 0; s < 2; s++)
                #pragma unroll
                for (int d = 0; d < 2; d++)
                    #pragma unroll
                    for (int j = 0; j < 8; j++)
                        acc[s][d][j] += av[s][d] * bv[j];
        }

        // epilogue: relu(acc + u + v), accumulate over s into agg
        float vv[2][8];
        #pragma unroll
        for (int d = 0; d < 2; d++) {
            const float4 v0 = *(const float4*)(sV + (trow * 2 + d) * 128 + col);
            const float4 v1 = *(const float4*)(sV + (trow * 2 + d) * 128 + col + 4);
            vv[d][0] = v0.x; vv[d][1] = v0.y; vv[d][2] = v0.z; vv[d][3] = v0.w;
            vv[d][4] = v1.x; vv[d][5] = v1.y; vv[d][6] = v1.z; vv[d][7] = v1.w;
        }
        #pragma unroll
        for (int s = 0; s < 2; s++) {
            const float4 u0 = *(const float4*)(sU + s * 128 + col);
            const float4 u1 = *(const float4*)(sU + s * 128 + col + 4);
            const float uu[8] = {u0.x, u0.y, u0.z, u0.w, u1.x, u1.y, u1.z, u1.w};
            #pragma unroll
            for (int d = 0; d < 2; d++)
                #pragma unroll
                for (int j = 0; j < 8; j++) {
                    const float val = acc[s][d][j] + uu[j] + vv[d][j];
                    agg[d][j] += fmaxf(val, 0.f);
                }
        }
    }

    // store partial agg (scaled by 1/deg) into this split's buffer
    const float scale = 1.f / (float)n_src;
    float* aggbuf = g_agg + (size_t)split * (BB * NN * DD);
    #pragma unroll
    for (int d = 0; d < 2; d++) {
        const int dg = d0 + trow * 2 + d;
        if (dg < n_dst) {
            float* base = aggbuf + ((size_t)b * NN + doff + dg) * DD + col;
            const float4 o0 = make_float4(agg[d][0] * scale, agg[d][1] * scale,
                                          agg[d][2] * scale, agg[d][3] * scale);
            const float4 o1 = make_float4(agg[d][4] * scale, agg[d][5] * scale,
                                          agg[d][6] * scale, agg[d][7] * scale);
            *(float4*)base       = o0;
            *(float4*)(base + 4) = o1;
        }
    }
}

// ---------------------------------------------------------------------------
// self kernel: x_out = relu(x @ Wself + b_self + agg0 + agg1)
// ---------------------------------------------------------------------------
__global__ __launch_bounds__(128) void self_kernel(const float* __restrict__ xin,
                                                   const float* __restrict__ wsl,
                                                   const float* __restrict__ bsl)
{
    __shared__ float xs[16][128];
    const int t    = threadIdx.x;
    const int row0 = blockIdx.x * 16;

    const float* x = (xin != nullptr) ? xin : g_x;

    {
        const float4* src = (const float4*)(x + (size_t)row0 * DD);
        float4* dst = (float4*)&xs[0][0];
        #pragma unroll
        for (int i = 0; i < 4; i++) dst[t + i * 128] = src[t + i * 128];
    }
    __syncthreads();

    float acc[16];
    #pragma unroll
    for (int r = 0; r < 16; r++) acc[r] = 0.f;

    #pragma unroll 4
    for (int k = 0; k < 128; k++) {
        const float w = __ldg(wsl + k * 128 + t);
        #pragma unroll
        for (int r = 0; r < 16; r++) acc[r] += xs[r][k] * w;
    }

    const float bias = bsl[t];
    #pragma unroll
    for (int r = 0; r < 16; r++) {
        const int row = row0 + r;
        const int n   = row % NN;
        float a = 0.f;
        if (n >= 64) {
            const size_t o = (size_t)row * DD + t;
            a = g_agg[o] + g_agg[(size_t)(BB * NN * DD) + o];
        }
        g_x[(size_t)row * DD + t] = fmaxf(acc[r] + bias + a, 0.f);
    }
}

// ---------------------------------------------------------------------------
// head kernel: per batch b -> mean over nodes, 2x relu MLP, final [128x10]
// ---------------------------------------------------------------------------
__global__ __launch_bounds__(128) void head_kernel(const float* __restrict__ w1,
                                                   const float* __restrict__ b1,
                                                   const float* __restrict__ w2,
                                                   const float* __restrict__ b2,
                                                   const float* __restrict__ w3,
                                                   const float* __restrict__ b3,
                                                   float* __restrict__ out)
{
    __shared__ float g[128];
    __shared__ float h[128];
    const int b = blockIdx.x;
    const int t = threadIdx.x;

    // mean over 458 nodes
    float s = 0.f;
    const float* xb = g_x + (size_t)b * NN * DD;
    for (int n = 0; n < NN; n++) s += xb[(size_t)n * DD + t];
    g[t] = s * (1.f / (float)NN);
    __syncthreads();

    // layer 1
    float acc = 0.f;
    #pragma unroll 4
    for (int k = 0; k < 128; k++) acc += g[k] * __ldg(w1 + k * 128 + t);
    h[t] = fmaxf(acc + b1[t], 0.f);
    __syncthreads();

    // layer 2
    acc = 0.f;
    #pragma unroll 4
    for (int k = 0; k < 128; k++) acc += h[k] * __ldg(w2 + k * 128 + t);
    __syncthreads();
    g[t] = fmaxf(acc + b2[t], 0.f);
    __syncthreads();

    // output projection [128 x 10]
    if (t < 10) {
        float o = b3[t];
        for (int k = 0; k < 128; k++) o += g[k] * __ldg(w3 + k * 10 + t);
        out[b * 10 + t] = o;
    }
}

// ---------------------------------------------------------------------------
// launch
// ---------------------------------------------------------------------------
extern "C" void kernel_launch(void* const* d_in, const int* in_sizes, int n_in,
                              void* d_out, int out_size)
{
    (void)in_sizes; (void)n_in; (void)out_size;
    const float* node_features = (const float*)d_in[0];
    const float* edge_attr     = (const float*)d_in[1];
    const float* w_msg         = (const float*)d_in[2];
    const float* b_msg         = (const float*)d_in[3];
    const float* w_self        = (const float*)d_in[4];
    const float* b_self        = (const float*)d_in[5];
    const float* w1            = (const float*)d_in[6];
    const float* b1            = (const float*)d_in[7];
    const float* w2            = (const float*)d_in[8];
    const float* b2            = (const float*)d_in[9];
    const float* w3            = (const float*)d_in[10];
    const float* b3            = (const float*)d_in[11];
    float* out = (float*)d_out;

    const int smem_bytes = EDGE_SMEM_FLOATS * (int)sizeof(float);
    cudaFuncSetAttribute(edge_kernel, cudaFuncAttributeMaxDynamicSharedMemorySize,
                         smem_bytes);

    for (int l = 0; l < 3; l++) {
        const float* xin = (l == 0) ? node_features : nullptr;
        const float* wl  = w_msg  + (size_t)l * 384 * 128;
        const float* bl  = b_msg  + (size_t)l * 128;
        const float* wsl = w_self + (size_t)l * 128 * 128;
        const float* bsl = b_self + (size_t)l * 128;

        uv_kernel<<<458, 128>>>(xin, wl, bl);
        edge_kernel<<<416, 256, smem_bytes>>>(edge_attr, wl);
        self_kernel<<<458, 128>>>(xin, wsl, bsl);
    }
    head_kernel<<<16, 128>>>(w1, b1, w2, b2, w3, b3, out);
}

// round 3
// speedup vs baseline: 6.0540x; 6.0540x over previous
#include <cuda_runtime.h>
#include <cstdint>
#include <cstddef>

#define BB 16
#define NN 458
#define DD 128
#define EE 42240

// ---------------------------------------------------------------------------
// Scratch (device globals; no allocation allowed)
// ---------------------------------------------------------------------------
__device__ float g_x  [BB * NN * DD];        // current node features
__device__ float g_u  [BB * NN * DD];        // x @ W_src
__device__ float g_v  [BB * NN * DD];        // x @ W_dst + b_msg
__device__ float g_agg[4 * BB * NN * DD];    // four partial agg buffers (src chunks)

#define AGG_STRIDE (BB * NN * DD)

// ---------------------------------------------------------------------------
// helpers
// ---------------------------------------------------------------------------
__device__ __forceinline__ float to_tf32(float x) {
    uint32_t u;
    asm("cvt.rna.tf32.f32 %0, %1;" : "=r"(u) : "f"(x));
    return __uint_as_float(u);
}

__device__ __forceinline__ void mma8(float& c0, float& c1, float& c2, float& c3,
                                     uint32_t a0, uint32_t a1, uint32_t a2, uint32_t a3,
                                     uint32_t b0, uint32_t b1) {
    asm volatile(
        "mma.sync.aligned.m16n8k8.row.col.f32.tf32.tf32.f32 "
        "{%0,%1,%2,%3},{%4,%5,%6,%7},{%8,%9},{%0,%1,%2,%3};"
        : "+f"(c0), "+f"(c1), "+f"(c2), "+f"(c3)
        : "r"(a0), "r"(a1), "r"(a2), "r"(a3), "r"(b0), "r"(b1));
}

// ---------------------------------------------------------------------------
// uv kernel: u = x @ Wsrc ; v = x @ Wdst + b_msg     (rows = B*N, 16 rows/CTA)
// ---------------------------------------------------------------------------
__global__ __launch_bounds__(128) void uv_kernel(const float* __restrict__ xin,
                                                 const float* __restrict__ wl,
                                                 const float* __restrict__ bl)
{
    __shared__ float xs[16][128];
    const int t    = threadIdx.x;
    const int row0 = blockIdx.x * 16;

    const float* x = (xin != nullptr) ? xin : g_x;

    {
        const float4* src = (const float4*)(x + (size_t)row0 * DD);
        float4* dst = (float4*)&xs[0][0];
        #pragma unroll
        for (int i = 0; i < 4; i++) dst[t + i * 128] = src[t + i * 128];
    }
    __syncthreads();

    float au[16], av[16];
    #pragma unroll
    for (int r = 0; r < 16; r++) { au[r] = 0.f; av[r] = 0.f; }

    #pragma unroll 4
    for (int k = 0; k < 128; k++) {
        const float wu = __ldg(wl + k * 128 + t);
        const float wv = __ldg(wl + (128 + k) * 128 + t);
        #pragma unroll
        for (int r = 0; r < 16; r++) {
            const float xv = xs[r][k];
            au[r] += xv * wu;
            av[r] += xv * wv;
        }
    }

    const float bias = bl[t];
    #pragma unroll
    for (int r = 0; r < 16; r++) {
        const size_t o = (size_t)(row0 + r) * DD + t;
        g_u[o] = au[r];
        g_v[o] = av[r] + bias;
    }
}

// ---------------------------------------------------------------------------
// edge kernel (tensor cores, tf32):
// CTA = (batch, block, 64-dst tile, 1/4-src chunk). For each src s in chunk:
//   acc = Etile(s, d0..d0+63) @ Wedge            (mma.sync tf32)
//   agg += relu(acc + u[s] + v[d])               (register accumulation)
// Final: g_agg[chunk] += agg / n_src  (distinct region per CTA; no atomics)
//
// smem: Wedge [128][136] tf32, A tiles double-buffered [2][64][132] tf32,
//       V tile [64][132] fp32, U rows [2][128] fp32.
// ---------------------------------------------------------------------------
#define SW_OFF 0
#define SA_OFF (128 * 136)
#define SV_OFF (SA_OFF + 2 * 64 * 132)
#define SU_OFF (SV_OFF + 64 * 132)
#define EDGE_SMEM_FLOATS (SU_OFF + 2 * 128)

__global__ __launch_bounds__(256, 1) void edge_kernel(const float* __restrict__ edge_attr,
                                                      const float* __restrict__ wl)
{
    extern __shared__ float sm[];
    float* sW = sm + SW_OFF;
    float* sA = sm + SA_OFF;
    float* sV = sm + SV_OFF;
    float* sU = sm + SU_OFF;

    const int tid = threadIdx.x;
    const int bx  = blockIdx.x;
    const int b   = bx / 28;
    const int it  = bx % 28;

    int lb, dtile, chunk;
    if      (it < 8)  { lb = 0; dtile = it >> 2;        chunk = it & 3; }
    else if (it < 16) { lb = 1; dtile = (it - 8) >> 2;  chunk = it & 3; }
    else if (it < 24) { lb = 2; dtile = (it - 16) >> 2; chunk = it & 3; }
    else              { lb = 3; dtile = 0;              chunk = it - 24; }

    const int nsrc_a[4] = {64, 128, 128, 128};
    const int ndst_a[4] = {128, 128, 128, 10};
    const int eb_a  [4] = {0, 8192, 24576, 40960};
    const int so_a  [4] = {0, 64, 192, 320};
    const int do_a  [4] = {64, 192, 320, 448};

    const int n_src = nsrc_a[lb];
    const int n_dst = ndst_a[lb];
    const int ebase = eb_a[lb];
    const int soff  = so_a[lb];
    const int doff  = do_a[lb];
    const int d0    = dtile * 64;

    const int iters   = n_src >> 2;
    const int s_begin = chunk * iters;

    // ---- stage Wedge (rows 256..383 of w_msg[l]) as tf32, pad 136 ----
    {
        const float* wedge = wl + 256 * 128;
        for (int i = tid; i < 4096; i += 256) {
            const int row = i >> 5, c4 = i & 31;
            float4 w = *(const float4*)(wedge + row * 128 + c4 * 4);
            w.x = to_tf32(w.x); w.y = to_tf32(w.y);
            w.z = to_tf32(w.z); w.w = to_tf32(w.w);
            *(float4*)(sW + row * 136 + c4 * 4) = w;
        }
    }
    // ---- stage V tile (fp32), zero-fill masked rows ----
    for (int i = tid; i < 2048; i += 256) {
        const int row = i >> 5, c4 = i & 31;
        float4 v4 = make_float4(0.f, 0.f, 0.f, 0.f);
        if (d0 + row < n_dst)
            v4 = *(const float4*)(g_v + ((size_t)b * NN + doff + d0 + row) * DD + c4 * 4);
        *(float4*)(sV + row * 132 + c4 * 4) = v4;
    }
    // ---- prologue: stage A(s_begin) + u(s_begin) into buffer 0 ----
    {
        const int s = s_begin;
        const float* eb = edge_attr + ((size_t)b * EE + ebase + (size_t)s * n_dst + d0) * DD;
        #pragma unroll
        for (int j = 0; j < 8; j++) {
            const int idx = tid + 256 * j;
            const int row = idx >> 5, c4 = idx & 31;
            float4 a = make_float4(0.f, 0.f, 0.f, 0.f);
            if (d0 + row < n_dst)
                a = *(const float4*)(eb + (size_t)row * DD + c4 * 4);
            a.x = to_tf32(a.x); a.y = to_tf32(a.y);
            a.z = to_tf32(a.z); a.w = to_tf32(a.w);
            *(float4*)(sA + row * 132 + c4 * 4) = a;
        }
        if (tid < 32)
            *(float4*)(sU + tid * 4) =
                *(const float4*)(g_u + ((size_t)b * NN + soff + s) * DD + tid * 4);
    }
    __syncthreads();

    // ---- per-warp tiling ----
    const int w    = tid >> 5;
    const int lane = tid & 31;
    const int wm   = w & 1;          // 0..1  (32 dst rows each)
    const int wn   = w >> 1;         // 0..3  (32 cols each)
    const int g    = lane >> 2;
    const int tig  = lane & 3;

    float agg[2][4][4];
    #pragma unroll
    for (int mt = 0; mt < 2; mt++)
        #pragma unroll
        for (int nt = 0; nt < 4; nt++)
            #pragma unroll
            for (int r = 0; r < 4; r++) agg[mt][nt][r] = 0.f;

    const uint32_t* sWu = (const uint32_t*)sW;

    for (int i = 0; i < iters; i++) {
        const int p = i & 1;
        const bool have_next = (i + 1 < iters);

        // prefetch next A tile + u row into registers (LDGs in flight over compute)
        float4 rA[8];
        float4 rU;
        if (have_next) {
            const int s = s_begin + i + 1;
            const float* eb = edge_attr + ((size_t)b * EE + ebase + (size_t)s * n_dst + d0) * DD;
            #pragma unroll
            for (int j = 0; j < 8; j++) {
                const int idx = tid + 256 * j;
                const int row = idx >> 5, c4 = idx & 31;
                if (d0 + row < n_dst)
                    rA[j] = *(const float4*)(eb + (size_t)row * DD + c4 * 4);
                else
                    rA[j] = make_float4(0.f, 0.f, 0.f, 0.f);
            }
            if (tid < 32)
                rU = *(const float4*)(g_u + ((size_t)b * NN + soff + s) * DD + tid * 4);
        }

        // ---- GEMM: acc = A(64x128) @ W(128x128), this warp's 32x32 slice ----
        float acc[2][4][4];
        #pragma unroll
        for (int mt = 0; mt < 2; mt++)
            #pragma unroll
            for (int nt = 0; nt < 4; nt++)
                #pragma unroll
                for (int r = 0; r < 4; r++) acc[mt][nt][r] = 0.f;

        const uint32_t* As = (const uint32_t*)(sA + p * (64 * 132));

        #pragma unroll
        for (int ks = 0; ks < 16; ks++) {
            uint32_t bf[4][2];
            #pragma unroll
            for (int nt = 0; nt < 4; nt++) {
                const int n = wn * 32 + nt * 8 + g;
                bf[nt][0] = sWu[(ks * 8 + tig) * 136 + n];
                bf[nt][1] = sWu[(ks * 8 + tig + 4) * 136 + n];
            }
            uint32_t af[2][4];
            #pragma unroll
            for (int mt = 0; mt < 2; mt++) {
                const int base = (wm * 32 + mt * 16 + g) * 132 + ks * 8;
                af[mt][0] = As[base + tig];
                af[mt][1] = As[base + 8 * 132 + tig];
                af[mt][2] = As[base + tig + 4];
                af[mt][3] = As[base + 8 * 132 + tig + 4];
            }
            #pragma unroll
            for (int mt = 0; mt < 2; mt++)
                #pragma unroll
                for (int nt = 0; nt < 4; nt++)
                    mma8(acc[mt][nt][0], acc[mt][nt][1], acc[mt][nt][2], acc[mt][nt][3],
                         af[mt][0], af[mt][1], af[mt][2], af[mt][3],
                         bf[nt][0], bf[nt][1]);
        }

        // ---- epilogue: agg += relu(acc + u + v) ----
        const float* sUp = sU + p * 128;
        #pragma unroll
        for (int nt = 0; nt < 4; nt++) {
            const int col = wn * 32 + nt * 8 + 2 * tig;
            const float2 uu = *(const float2*)(sUp + col);
            #pragma unroll
            for (int mt = 0; mt < 2; mt++) {
                const int r0 = wm * 32 + mt * 16 + g;
                const float2 v0 = *(const float2*)(sV + r0 * 132 + col);
                const float2 v1 = *(const float2*)(sV + (r0 + 8) * 132 + col);
                agg[mt][nt][0] += fmaxf(acc[mt][nt][0] + uu.x + v0.x, 0.f);
                agg[mt][nt][1] += fmaxf(acc[mt][nt][1] + uu.y + v0.y, 0.f);
                agg[mt][nt][2] += fmaxf(acc[mt][nt][2] + uu.x + v1.x, 0.f);
                agg[mt][nt][3] += fmaxf(acc[mt][nt][3] + uu.y + v1.y, 0.f);
            }
        }

        // ---- write next tile (tf32) into the other buffer ----
        if (have_next) {
            float* sAn = sA + (p ^ 1) * (64 * 132);
            #pragma unroll
            for (int j = 0; j < 8; j++) {
                const int idx = tid + 256 * j;
                const int row = idx >> 5, c4 = idx & 31;
                float4 a = rA[j];
                a.x = to_tf32(a.x); a.y = to_tf32(a.y);
                a.z = to_tf32(a.z); a.w = to_tf32(a.w);
                *(float4*)(sAn + row * 132 + c4 * 4) = a;
            }
            if (tid < 32)
                *(float4*)(sU + (p ^ 1) * 128 + tid * 4) = rU;
        }
        __syncthreads();
    }

    // ---- store partial agg (scaled) into this chunk's buffer ----
    const float scale = 1.f / (float)n_src;
    float* aggbuf = g_agg + (size_t)chunk * AGG_STRIDE;
    #pragma unroll
    for (int mt = 0; mt < 2; mt++) {
        const int rloc = wm * 32 + mt * 16 + g;
        #pragma unroll
        for (int nt = 0; nt < 4; nt++) {
            const int col = wn * 32 + nt * 8 + 2 * tig;
            const int dg0 = d0 + rloc;
            const int dg1 = dg0 + 8;
            if (dg0 < n_dst) {
                float2 o = make_float2(agg[mt][nt][0] * scale, agg[mt][nt][1] * scale);
                *(float2*)(aggbuf + ((size_t)b * NN + doff + dg0) * DD + col) = o;
            }
            if (dg1 < n_dst) {
                float2 o = make_float2(agg[mt][nt][2] * scale, agg[mt][nt][3] * scale);
                *(float2*)(aggbuf + ((size_t)b * NN + doff + dg1) * DD + col) = o;
            }
        }
    }
}

// ---------------------------------------------------------------------------
// self kernel: x_out = relu(x @ Wself + b_self + sum_c agg[c])
// ---------------------------------------------------------------------------
__global__ __launch_bounds__(128) void self_kernel(const float* __restrict__ xin,
                                                   const float* __restrict__ wsl,
                                                   const float* __restrict__ bsl)
{
    __shared__ float xs[16][128];
    const int t    = threadIdx.x;
    const int row0 = blockIdx.x * 16;

    const float* x = (xin != nullptr) ? xin : g_x;

    {
        const float4* src = (const float4*)(x + (size_t)row0 * DD);
        float4* dst = (float4*)&xs[0][0];
        #pragma unroll
        for (int i = 0; i < 4; i++) dst[t + i * 128] = src[t + i * 128];
    }
    __syncthreads();

    float acc[16];
    #pragma unroll
    for (int r = 0; r < 16; r++) acc[r] = 0.f;

    #pragma unroll 4
    for (int k = 0; k < 128; k++) {
        const float w = __ldg(wsl + k * 128 + t);
        #pragma unroll
        for (int r = 0; r < 16; r++) acc[r] += xs[r][k] * w;
    }

    const float bias = bsl[t];
    #pragma unroll
    for (int r = 0; r < 16; r++) {
        const int row = row0 + r;
        const int n   = row % NN;
        float a = 0.f;
        if (n >= 64) {
            const size_t o = (size_t)row * DD + t;
            a = g_agg[o] + g_agg[AGG_STRIDE + o]
              + g_agg[2 * (size_t)AGG_STRIDE + o] + g_agg[3 * (size_t)AGG_STRIDE + o];
        }
        g_x[(size_t)row * DD + t] = fmaxf(acc[r] + bias + a, 0.f);
    }
}

// ---------------------------------------------------------------------------
// head kernel: per batch b -> mean over nodes, 2x relu MLP, final [128x10]
// ---------------------------------------------------------------------------
__global__ __launch_bounds__(128) void head_kernel(const float* __restrict__ w1,
                                                   const float* __restrict__ b1,
                                                   const float* __restrict__ w2,
                                                   const float* __restrict__ b2,
                                                   const float* __restrict__ w3,
                                                   const float* __restrict__ b3,
                                                   float* __restrict__ out)
{
    __shared__ float g[128];
    __shared__ float h[128];
    const int b = blockIdx.x;
    const int t = threadIdx.x;

    float s = 0.f;
    const float* xb = g_x + (size_t)b * NN * DD;
    for (int n = 0; n < NN; n++) s += xb[(size_t)n * DD + t];
    g[t] = s * (1.f / (float)NN);
    __syncthreads();

    float acc = 0.f;
    #pragma unroll 4
    for (int k = 0; k < 128; k++) acc += g[k] * __ldg(w1 + k * 128 + t);
    h[t] = fmaxf(acc + b1[t], 0.f);
    __syncthreads();

    acc = 0.f;
    #pragma unroll 4
    for (int k = 0; k < 128; k++) acc += h[k] * __ldg(w2 + k * 128 + t);
    __syncthreads();
    g[t] = fmaxf(acc + b2[t], 0.f);
    __syncthreads();

    if (t < 10) {
        float o = b3[t];
        for (int k = 0; k < 128; k++) o += g[k] * __ldg(w3 + k * 10 + t);
        out[b * 10 + t] = o;
    }
}

// ---------------------------------------------------------------------------
// launch
// ---------------------------------------------------------------------------
extern "C" void kernel_launch(void* const* d_in, const int* in_sizes, int n_in,
                              void* d_out, int out_size)
{
    (void)in_sizes; (void)n_in; (void)out_size;
    const float* node_features = (const float*)d_in[0];
    const float* edge_attr     = (const float*)d_in[1];
    const float* w_msg         = (const float*)d_in[2];
    const float* b_msg         = (const float*)d_in[3];
    const float* w_self        = (const float*)d_in[4];
    const float* b_self        = (const float*)d_in[5];
    const float* w1            = (const float*)d_in[6];
    const float* b1            = (const float*)d_in[7];
    const float* w2            = (const float*)d_in[8];
    const float* b2            = (const float*)d_in[9];
    const float* w3            = (const float*)d_in[10];
    const float* b3            = (const float*)d_in[11];
    float* out = (float*)d_out;

    const int smem_bytes = EDGE_SMEM_FLOATS * (int)sizeof(float);
    cudaFuncSetAttribute(edge_kernel, cudaFuncAttributeMaxDynamicSharedMemorySize,
                         smem_bytes);

    for (int l = 0; l < 3; l++) {
        const float* xin = (l == 0) ? node_features : nullptr;
        const float* wl  = w_msg  + (size_t)l * 384 * 128;
        const float* bl  = b_msg  + (size_t)l * 128;
        const float* wsl = w_self + (size_t)l * 128 * 128;
        const float* bsl = b_self + (size_t)l * 128;

        uv_kernel<<<458, 128>>>(xin, wl, bl);
        edge_kernel<<<448, 256, smem_bytes>>>(edge_attr, wl);
        self_kernel<<<458, 128>>>(xin, wsl, bsl);
    }
    head_kernel<<<16, 128>>>(w1, b1, w2, b2, w3, b3, out);
}

// round 4
// speedup vs baseline: 7.5461x; 1.2465x over previous
#include <cuda_runtime.h>
#include <cuda_bf16.h>
#include <cstdint>
#include <cstddef>

#define BB 16
#define NN 458
#define DD 128
#define EE 42240
#define AGG_STRIDE (BB * NN * DD)

// ---------------------------------------------------------------------------
// Scratch (device globals; no allocation allowed)
// ---------------------------------------------------------------------------
__device__ float g_x  [BB * NN * DD];        // current node features
__device__ float g_u  [BB * NN * DD];        // x @ W_src
__device__ float g_v  [BB * NN * DD];        // x @ W_dst + b_msg
__device__ float g_agg[4 * BB * NN * DD];    // four partial agg buffers (src chunks)

// ---------------------------------------------------------------------------
// helpers
// ---------------------------------------------------------------------------
__device__ __forceinline__ uint32_t packbf(float lo, float hi) {
    uint32_t r;
    asm("cvt.rn.bf16x2.f32 %0, %1, %2;" : "=r"(r) : "f"(hi), "f"(lo));
    return r;
}

__device__ __forceinline__ void mma16(float& c0, float& c1, float& c2, float& c3,
                                      uint32_t a0, uint32_t a1, uint32_t a2, uint32_t a3,
                                      uint32_t b0, uint32_t b1) {
    asm volatile(
        "mma.sync.aligned.m16n8k16.row.col.f32.bf16.bf16.f32 "
        "{%0,%1,%2,%3},{%4,%5,%6,%7},{%8,%9},{%0,%1,%2,%3};"
        : "+f"(c0), "+f"(c1), "+f"(c2), "+f"(c3)
        : "r"(a0), "r"(a1), "r"(a2), "r"(a3), "r"(b0), "r"(b1));
}

// ---------------------------------------------------------------------------
// edge kernel (bf16 tensor cores, occ 2):
// CTA = (batch, block, 64-dst tile, 1/4-src chunk). For each src s:
//   acc = Etile(s, d0..d0+63) @ Wedge   (mma.m16n8k16 bf16, fp32 accum)
//   agg += relu(acc + u[s] + v[d])      (fp32 register accumulation)
// smem (words): sWp [64 kpair][136] packed bf16x2 (conflict-free for B frags)
//               sAp [2][64 row][68]  packed bf16x2 (conflict-free for A frags)
//               sV  [64][132] fp32, sU [2][128] fp32
// ---------------------------------------------------------------------------
#define EW_SW 0
#define EW_SA 8704                 // 64*136
#define EW_SV (EW_SA + 2 * 4352)   // 4352 = 64*68
#define EW_SU (EW_SV + 64 * 132)
#define EDGE_SMEM_WORDS (EW_SU + 2 * 128)
#define EDGE_SMEM_BYTES (EDGE_SMEM_WORDS * 4)

__global__ __launch_bounds__(256, 2) void edge_kernel(const float* __restrict__ edge_attr,
                                                      const float* __restrict__ wl)
{
    extern __shared__ uint32_t smw[];
    uint32_t* sWp = smw + EW_SW;
    uint32_t* sAp = smw + EW_SA;
    float* sV = (float*)(smw + EW_SV);
    float* sU = (float*)(smw + EW_SU);

    const int tid = threadIdx.x;
    const int bx  = blockIdx.x;
    const int b   = bx / 28;
    const int it  = bx % 28;

    int lb, dtile, chunk;
    if      (it < 8)  { lb = 0; dtile = it >> 2;        chunk = it & 3; }
    else if (it < 16) { lb = 1; dtile = (it - 8) >> 2;  chunk = it & 3; }
    else if (it < 24) { lb = 2; dtile = (it - 16) >> 2; chunk = it & 3; }
    else              { lb = 3; dtile = 0;              chunk = it - 24; }

    const int nsrc_a[4] = {64, 128, 128, 128};
    const int ndst_a[4] = {128, 128, 128, 10};
    const int eb_a  [4] = {0, 8192, 24576, 40960};
    const int so_a  [4] = {0, 64, 192, 320};
    const int do_a  [4] = {64, 192, 320, 448};

    const int n_src = nsrc_a[lb];
    const int n_dst = ndst_a[lb];
    const int ebase = eb_a[lb];
    const int soff  = so_a[lb];
    const int doff  = do_a[lb];
    const int d0    = dtile * 64;

    const int iters   = n_src >> 2;
    const int s_begin = chunk * iters;

    // ---- stage Wedge (rows 256..383 of w_msg[l]) packed bf16 pairs along k ----
    {
        const float* wedge = wl + 256 * 128;
        for (int i = tid; i < 8192; i += 256) {
            const int kp = i >> 7, n = i & 127;
            const float w0 = wedge[(2 * kp) * 128 + n];
            const float w1 = wedge[(2 * kp + 1) * 128 + n];
            sWp[kp * 136 + n] = packbf(w0, w1);
        }
    }
    // ---- stage V tile (fp32), zero-fill masked rows ----
    for (int i = tid; i < 2048; i += 256) {
        const int row = i >> 5, c4 = i & 31;
        float4 v4 = make_float4(0.f, 0.f, 0.f, 0.f);
        if (d0 + row < n_dst)
            v4 = *(const float4*)(g_v + ((size_t)b * NN + doff + d0 + row) * DD + c4 * 4);
        *(float4*)(sV + row * 132 + c4 * 4) = v4;
    }
    // ---- prologue: stage A(s_begin) + u(s_begin) into buffer 0 ----
    {
        const int s = s_begin;
        const float* eb = edge_attr + ((size_t)b * EE + ebase + (size_t)s * n_dst + d0) * DD;
        #pragma unroll
        for (int j = 0; j < 8; j++) {
            const int idx = tid + 256 * j;
            const int row = idx >> 5, c4 = idx & 31;
            float4 a = make_float4(0.f, 0.f, 0.f, 0.f);
            if (d0 + row < n_dst)
                a = *(const float4*)(eb + (size_t)row * DD + c4 * 4);
            *(uint2*)(sAp + row * 68 + 2 * c4) =
                make_uint2(packbf(a.x, a.y), packbf(a.z, a.w));
        }
        if (tid < 32)
            *(float4*)(sU + tid * 4) =
                *(const float4*)(g_u + ((size_t)b * NN + soff + s) * DD + tid * 4);
    }
    __syncthreads();

    // ---- per-warp tiling ----
    const int w    = tid >> 5;
    const int lane = tid & 31;
    const int wm   = w & 1;          // 0..1  (32 dst rows each)
    const int wn   = w >> 1;         // 0..3  (32 cols each)
    const int g    = lane >> 2;
    const int tig  = lane & 3;

    float agg[2][4][4];
    #pragma unroll
    for (int mt = 0; mt < 2; mt++)
        #pragma unroll
        for (int nt = 0; nt < 4; nt++)
            #pragma unroll
            for (int r = 0; r < 4; r++) agg[mt][nt][r] = 0.f;

    const int myrow = tid >> 5;          // for staging: rows (tid>>5) + 8*jj
    const int myc4  = tid & 31;

    for (int i = 0; i < iters; i++) {
        const int p = i & 1;
        const bool have_next = (i + 1 < iters);
        const float* ebn = edge_attr +
            ((size_t)b * EE + ebase + (size_t)(s_begin + i + 1) * n_dst + d0) * DD;
        uint32_t* sAn = sAp + (p ^ 1) * 4352;

        // prefetch u(next) + first half of A(next): rows 0..31
        float4 rU;
        float4 rA[4];
        if (have_next) {
            if (tid < 32)
                rU = *(const float4*)(g_u +
                        ((size_t)b * NN + soff + s_begin + i + 1) * DD + tid * 4);
            #pragma unroll
            for (int j = 0; j < 4; j++) {
                const int row = myrow + 8 * j;
                if (d0 + row < n_dst)
                    rA[j] = *(const float4*)(ebn + (size_t)row * DD + myc4 * 4);
                else
                    rA[j] = make_float4(0.f, 0.f, 0.f, 0.f);
            }
        }

        float acc[2][4][4];
        #pragma unroll
        for (int mt = 0; mt < 2; mt++)
            #pragma unroll
            for (int nt = 0; nt < 4; nt++)
                #pragma unroll
                for (int r = 0; r < 4; r++) acc[mt][nt][r] = 0.f;

        const uint32_t* As = sAp + p * 4352;

        // ---- mma first half: ks 0..3 ----
        #pragma unroll
        for (int ks = 0; ks < 4; ks++) {
            uint32_t bf[4][2];
            #pragma unroll
            for (int nt = 0; nt < 4; nt++) {
                const int n = wn * 32 + nt * 8 + g;
                bf[nt][0] = sWp[(ks * 8 + tig) * 136 + n];
                bf[nt][1] = sWp[(ks * 8 + tig + 4) * 136 + n];
            }
            uint32_t af[2][4];
            #pragma unroll
            for (int mt = 0; mt < 2; mt++) {
                const int base = (wm * 32 + mt * 16 + g) * 68 + ks * 8;
                af[mt][0] = As[base + tig];
                af[mt][1] = As[base + 8 * 68 + tig];
                af[mt][2] = As[base + tig + 4];
                af[mt][3] = As[base + 8 * 68 + tig + 4];
            }
            #pragma unroll
            for (int mt = 0; mt < 2; mt++)
                #pragma unroll
                for (int nt = 0; nt < 4; nt++)
                    mma16(acc[mt][nt][0], acc[mt][nt][1], acc[mt][nt][2], acc[mt][nt][3],
                          af[mt][0], af[mt][1], af[mt][2], af[mt][3],
                          bf[nt][0], bf[nt][1]);
        }

        // issue second-half loads, then store first half (writes to buffer p^1,
        // which no warp reads until after the trailing __syncthreads)
        if (have_next) {
            float4 rB[4];
            #pragma unroll
            for (int j = 0; j < 4; j++) {
                const int row = 32 + myrow + 8 * j;
                if (d0 + row < n_dst)
                    rB[j] = *(const float4*)(ebn + (size_t)row * DD + myc4 * 4);
                else
                    rB[j] = make_float4(0.f, 0.f, 0.f, 0.f);
            }
            #pragma unroll
            for (int j = 0; j < 4; j++) {
                const int row = myrow + 8 * j;
                *(uint2*)(sAn + row * 68 + 2 * myc4) =
                    make_uint2(packbf(rA[j].x, rA[j].y), packbf(rA[j].z, rA[j].w));
                rA[j] = rB[j];
            }
        }

        // ---- mma second half: ks 4..7 ----
        #pragma unroll
        for (int ks = 4; ks < 8; ks++) {
            uint32_t bf[4][2];
            #pragma unroll
            for (int nt = 0; nt < 4; nt++) {
                const int n = wn * 32 + nt * 8 + g;
                bf[nt][0] = sWp[(ks * 8 + tig) * 136 + n];
                bf[nt][1] = sWp[(ks * 8 + tig + 4) * 136 + n];
            }
            uint32_t af[2][4];
            #pragma unroll
            for (int mt = 0; mt < 2; mt++) {
                const int base = (wm * 32 + mt * 16 + g) * 68 + ks * 8;
                af[mt][0] = As[base + tig];
                af[mt][1] = As[base + 8 * 68 + tig];
                af[mt][2] = As[base + tig + 4];
                af[mt][3] = As[base + 8 * 68 + tig + 4];
            }
            #pragma unroll
            for (int mt = 0; mt < 2; mt++)
                #pragma unroll
                for (int nt = 0; nt < 4; nt++)
                    mma16(acc[mt][nt][0], acc[mt][nt][1], acc[mt][nt][2], acc[mt][nt][3],
                          af[mt][0], af[mt][1], af[mt][2], af[mt][3],
                          bf[nt][0], bf[nt][1]);
        }

        // store second half of next A + u(next)
        if (have_next) {
            #pragma unroll
            for (int j = 0; j < 4; j++) {
                const int row = 32 + myrow + 8 * j;
                *(uint2*)(sAn + row * 68 + 2 * myc4) =
                    make_uint2(packbf(rA[j].x, rA[j].y), packbf(rA[j].z, rA[j].w));
            }
            if (tid < 32)
                *(float4*)(sU + (p ^ 1) * 128 + tid * 4) = rU;
        }

        // ---- epilogue: agg += relu(acc + u + v) ----
        const float* sUp = sU + p * 128;
        #pragma unroll
        for (int nt = 0; nt < 4; nt++) {
            const int col = wn * 32 + nt * 8 + 2 * tig;
            const float2 uu = *(const float2*)(sUp + col);
            #pragma unroll
            for (int mt = 0; mt < 2; mt++) {
                const int r0 = wm * 32 + mt * 16 + g;
                const float2 v0 = *(const float2*)(sV + r0 * 132 + col);
                const float2 v1 = *(const float2*)(sV + (r0 + 8) * 132 + col);
                agg[mt][nt][0] += fmaxf(acc[mt][nt][0] + uu.x + v0.x, 0.f);
                agg[mt][nt][1] += fmaxf(acc[mt][nt][1] + uu.y + v0.y, 0.f);
                agg[mt][nt][2] += fmaxf(acc[mt][nt][2] + uu.x + v1.x, 0.f);
                agg[mt][nt][3] += fmaxf(acc[mt][nt][3] + uu.y + v1.y, 0.f);
            }
        }
        __syncthreads();
    }

    // ---- store partial agg (scaled) into this chunk's buffer ----
    const float scale = 1.f / (float)n_src;
    float* aggbuf = g_agg + (size_t)chunk * AGG_STRIDE;
    #pragma unroll
    for (int mt = 0; mt < 2; mt++) {
        const int rloc = wm * 32 + mt * 16 + g;
        #pragma unroll
        for (int nt = 0; nt < 4; nt++) {
            const int col = wn * 32 + nt * 8 + 2 * tig;
            const int dg0 = d0 + rloc;
            const int dg1 = dg0 + 8;
            if (dg0 < n_dst)
                *(float2*)(aggbuf + ((size_t)b * NN + doff + dg0) * DD + col) =
                    make_float2(agg[mt][nt][0] * scale, agg[mt][nt][1] * scale);
            if (dg1 < n_dst)
                *(float2*)(aggbuf + ((size_t)b * NN + doff + dg1) * DD + col) =
                    make_float2(agg[mt][nt][2] * scale, agg[mt][nt][3] * scale);
        }
    }
}

// ---------------------------------------------------------------------------
// fused self+uv kernel: 8 rows/CTA, 916 CTAs (more resident warps -> latency).
//   if wself: x_new = relu(x @ Wself + b_self + sum_c agg[c]); write g_x
//   else:     x_new = x                      (pure-uv mode for layer 0)
//   if wnext: u = x_new @ Wsrc ; v = x_new @ Wdst + b_msg  (next layer)
// ---------------------------------------------------------------------------
__global__ __launch_bounds__(128) void self_uv_kernel(const float* __restrict__ xin,
                                                      const float* __restrict__ wself,
                                                      const float* __restrict__ bself,
                                                      const float* __restrict__ wnext,
                                                      const float* __restrict__ bnext)
{
    __shared__ float xs[8][128];
    __shared__ float xn[8][128];
    const int t    = threadIdx.x;
    const int row0 = blockIdx.x * 8;

    const float* x = (xin != nullptr) ? xin : g_x;

    {
        const float4* src = (const float4*)(x + (size_t)row0 * DD);
        float4* dst = (float4*)&xs[0][0];
        dst[t]       = src[t];
        dst[t + 128] = src[t + 128];
    }
    __syncthreads();

    if (wself != nullptr) {
        float acc[8];
        #pragma unroll
        for (int r = 0; r < 8; r++) acc[r] = 0.f;
        #pragma unroll 8
        for (int k = 0; k < 128; k++) {
            const float w = __ldg(wself + k * 128 + t);
            #pragma unroll
            for (int r = 0; r < 8; r++) acc[r] += xs[r][k] * w;
        }
        const float bias = bself[t];
        #pragma unroll
        for (int r = 0; r < 8; r++) {
            const int row = row0 + r;
            const int n   = row % NN;
            float a = 0.f;
            if (n >= 64) {
                const size_t o = (size_t)row * DD + t;
                a = g_agg[o] + g_agg[AGG_STRIDE + o]
                  + g_agg[2 * (size_t)AGG_STRIDE + o] + g_agg[3 * (size_t)AGG_STRIDE + o];
            }
            const float xv = fmaxf(acc[r] + bias + a, 0.f);
            g_x[(size_t)row * DD + t] = xv;
            xn[r][t] = xv;
        }
    } else {
        #pragma unroll
        for (int r = 0; r < 8; r++) xn[r][t] = xs[r][t];
    }
    __syncthreads();

    if (wnext != nullptr) {
        float au[8], av[8];
        #pragma unroll
        for (int r = 0; r < 8; r++) { au[r] = 0.f; av[r] = 0.f; }
        #pragma unroll 4
        for (int k = 0; k < 128; k++) {
            const float wu = __ldg(wnext + k * 128 + t);
            const float wv = __ldg(wnext + (128 + k) * 128 + t);
            #pragma unroll
            for (int r = 0; r < 8; r++) {
                const float xv = xn[r][k];
                au[r] += xv * wu;
                av[r] += xv * wv;
            }
        }
        const float bias = bnext[t];
        #pragma unroll
        for (int r = 0; r < 8; r++) {
            const size_t o = (size_t)(row0 + r) * DD + t;
            g_u[o] = au[r];
            g_v[o] = av[r] + bias;
        }
    }
}

// ---------------------------------------------------------------------------
// head kernel: per batch b -> mean over nodes, 2x relu MLP, final [128x10]
// ---------------------------------------------------------------------------
__global__ __launch_bounds__(128) void head_kernel(const float* __restrict__ w1,
                                                   const float* __restrict__ b1,
                                                   const float* __restrict__ w2,
                                                   const float* __restrict__ b2,
                                                   const float* __restrict__ w3,
                                                   const float* __restrict__ b3,
                                                   float* __restrict__ out)
{
    __shared__ float g[128];
    __shared__ float h[128];
    const int b = blockIdx.x;
    const int t = threadIdx.x;

    float s = 0.f;
    const float* xb = g_x + (size_t)b * NN * DD;
    for (int n = 0; n < NN; n++) s += xb[(size_t)n * DD + t];
    g[t] = s * (1.f / (float)NN);
    __syncthreads();

    float acc = 0.f;
    #pragma unroll 4
    for (int k = 0; k < 128; k++) acc += g[k] * __ldg(w1 + k * 128 + t);
    h[t] = fmaxf(acc + b1[t], 0.f);
    __syncthreads();

    acc = 0.f;
    #pragma unroll 4
    for (int k = 0; k < 128; k++) acc += h[k] * __ldg(w2 + k * 128 + t);
    __syncthreads();
    g[t] = fmaxf(acc + b2[t], 0.f);
    __syncthreads();

    if (t < 10) {
        float o = b3[t];
        for (int k = 0; k < 128; k++) o += g[k] * __ldg(w3 + k * 10 + t);
        out[b * 10 + t] = o;
    }
}

// ---------------------------------------------------------------------------
// launch
// ---------------------------------------------------------------------------
extern "C" void kernel_launch(void* const* d_in, const int* in_sizes, int n_in,
                              void* d_out, int out_size)
{
    (void)in_sizes; (void)n_in; (void)out_size;
    const float* node_features = (const float*)d_in[0];
    const float* edge_attr     = (const float*)d_in[1];
    const float* w_msg         = (const float*)d_in[2];
    const float* b_msg         = (const float*)d_in[3];
    const float* w_self        = (const float*)d_in[4];
    const float* b_self        = (const float*)d_in[5];
    const float* w1            = (const float*)d_in[6];
    const float* b1            = (const float*)d_in[7];
    const float* w2            = (const float*)d_in[8];
    const float* b2            = (const float*)d_in[9];
    const float* w3            = (const float*)d_in[10];
    const float* b3            = (const float*)d_in[11];
    float* out = (float*)d_out;

    cudaFuncSetAttribute(edge_kernel, cudaFuncAttributeMaxDynamicSharedMemorySize,
                         EDGE_SMEM_BYTES);

    // layer-0 u,v (pure-uv mode)
    self_uv_kernel<<<916, 128>>>(node_features, nullptr, nullptr, w_msg, b_msg);

    for (int l = 0; l < 3; l++) {
        const float* wl  = w_msg + (size_t)l * 384 * 128;
        edge_kernel<<<448, 256, EDGE_SMEM_BYTES>>>(edge_attr, wl);

        const float* xin = (l == 0) ? node_features : nullptr;
        const float* wn  = (l < 2) ? w_msg + (size_t)(l + 1) * 384 * 128 : nullptr;
        const float* bn  = (l < 2) ? b_msg + (size_t)(l + 1) * 128 : nullptr;
        self_uv_kernel<<<916, 128>>>(xin, w_self + (size_t)l * 128 * 128,
                                     b_self + (size_t)l * 128, wn, bn);
    }
    head_kernel<<<16, 128>>>(w1, b1, w2, b2, w3, b3, out);
}

// round 6
// speedup vs baseline: 7.7563x; 1.0279x over previous
#include <cuda_runtime.h>
#include <cuda_bf16.h>
#include <cstdint>
#include <cstddef>

#define BB 16
#define NN 458
#define DD 128
#define EE 42240
#define AGG_STRIDE (BB * NN * DD)

// ---------------------------------------------------------------------------
// Scratch (device globals; no allocation allowed)
// ---------------------------------------------------------------------------
__device__ float g_x  [BB * NN * DD];        // current node features
__device__ float g_u  [BB * NN * DD];        // x @ W_src
__device__ float g_v  [BB * NN * DD];        // x @ W_dst + b_msg
__device__ float g_agg[4 * BB * NN * DD];    // four partial agg buffers (src chunks)

// ---------------------------------------------------------------------------
// helpers
// ---------------------------------------------------------------------------
__device__ __forceinline__ uint32_t packbf(float lo, float hi) {
    uint32_t r;
    asm("cvt.rn.bf16x2.f32 %0, %1, %2;" : "=r"(r) : "f"(hi), "f"(lo));
    return r;
}

__device__ __forceinline__ uint32_t smem_u32(const void* p) {
    uint32_t a;
    asm("{ .reg .u64 t; cvta.to.shared.u64 t, %1; cvt.u32.u64 %0, t; }"
        : "=r"(a) : "l"(p));
    return a;
}

__device__ __forceinline__ void mma16(float& c0, float& c1, float& c2, float& c3,
                                      uint32_t a0, uint32_t a1, uint32_t a2, uint32_t a3,
                                      uint32_t b0, uint32_t b1) {
    asm volatile(
        "mma.sync.aligned.m16n8k16.row.col.f32.bf16.bf16.f32 "
        "{%0,%1,%2,%3},{%4,%5,%6,%7},{%8,%9},{%0,%1,%2,%3};"
        : "+f"(c0), "+f"(c1), "+f"(c2), "+f"(c3)
        : "r"(a0), "r"(a1), "r"(a2), "r"(a3), "r"(b0), "r"(b1));
}

__device__ __forceinline__ void ldsm_x4(uint32_t& r0, uint32_t& r1, uint32_t& r2,
                                        uint32_t& r3, uint32_t addr) {
    asm volatile("ldmatrix.sync.aligned.m8n8.x4.shared.b16 {%0,%1,%2,%3}, [%4];"
                 : "=r"(r0), "=r"(r1), "=r"(r2), "=r"(r3) : "r"(addr));
}

// ---------------------------------------------------------------------------
// edge kernel (bf16 mma.sync, B-fragments hoisted to registers, ldmatrix A):
// CTA = (batch, block, 64-dst tile, 1/4-src chunk). For each src s:
//   acc = Etile(s, d0..d0+63) @ Wedge   (m16n8k16 bf16, fp32 accum)
//   agg += relu(acc + u[s] + v[d])      (fp32 register accumulation)
// smem (words): sWp [64 kpair][136] packed bf16x2 (one-time B-frag load)
//               sAp [2][64 row][68]  packed bf16x2 (LDSM-fed, conflict-free)
//               sV  [64][132] fp32, sU [2][128] fp32
// ---------------------------------------------------------------------------
#define EW_SW 0
#define EW_SA 8704                 // 64*136
#define EW_SV (EW_SA + 2 * 4352)   // 4352 = 64*68
#define EW_SU (EW_SV + 64 * 132)
#define EDGE_SMEM_WORDS (EW_SU + 2 * 128)
#define EDGE_SMEM_BYTES (EDGE_SMEM_WORDS * 4)

__global__ __launch_bounds__(256, 1) void edge_kernel(const float* __restrict__ edge_attr,
                                                      const float* __restrict__ wl)
{
    extern __shared__ uint32_t smw[];
    uint32_t* sWp = smw + EW_SW;
    uint32_t* sAp = smw + EW_SA;
    float* sV = (float*)(smw + EW_SV);
    float* sU = (float*)(smw + EW_SU);

    const int tid = threadIdx.x;
    const int bx  = blockIdx.x;
    const int b   = bx / 28;
    const int it  = bx % 28;

    int lb, dtile, chunk;
    if      (it < 8)  { lb = 0; dtile = it >> 2;        chunk = it & 3; }
    else if (it < 16) { lb = 1; dtile = (it - 8) >> 2;  chunk = it & 3; }
    else if (it < 24) { lb = 2; dtile = (it - 16) >> 2; chunk = it & 3; }
    else              { lb = 3; dtile = 0;              chunk = it - 24; }

    const int nsrc_a[4] = {64, 128, 128, 128};
    const int ndst_a[4] = {128, 128, 128, 10};
    const int eb_a  [4] = {0, 8192, 24576, 40960};
    const int so_a  [4] = {0, 64, 192, 320};
    const int do_a  [4] = {64, 192, 320, 448};

    const int n_src = nsrc_a[lb];
    const int n_dst = ndst_a[lb];
    const int ebase = eb_a[lb];
    const int soff  = so_a[lb];
    const int doff  = do_a[lb];
    const int d0    = dtile * 64;

    const int iters   = n_src >> 2;
    const int s_begin = chunk * iters;

    // ---- stage Wedge (rows 256..383 of w_msg[l]) packed bf16 pairs along k ----
    {
        const float* wedge = wl + 256 * 128;
        for (int i = tid; i < 8192; i += 256) {
            const int kp = i >> 7, n = i & 127;
            const float w0 = wedge[(2 * kp) * 128 + n];
            const float w1 = wedge[(2 * kp + 1) * 128 + n];
            sWp[kp * 136 + n] = packbf(w0, w1);
        }
    }
    // ---- stage V tile (fp32), zero-fill masked rows ----
    for (int i = tid; i < 2048; i += 256) {
        const int row = i >> 5, c4 = i & 31;
        float4 v4 = make_float4(0.f, 0.f, 0.f, 0.f);
        if (d0 + row < n_dst)
            v4 = *(const float4*)(g_v + ((size_t)b * NN + doff + d0 + row) * DD + c4 * 4);
        *(float4*)(sV + row * 132 + c4 * 4) = v4;
    }
    // ---- prologue: stage A(s_begin) + u(s_begin) into buffer 0 ----
    {
        const int s = s_begin;
        const float* eb = edge_attr + ((size_t)b * EE + ebase + (size_t)s * n_dst + d0) * DD;
        #pragma unroll
        for (int j = 0; j < 8; j++) {
            const int idx = tid + 256 * j;
            const int row = idx >> 5, c4 = idx & 31;
            float4 a = make_float4(0.f, 0.f, 0.f, 0.f);
            if (d0 + row < n_dst)
                a = *(const float4*)(eb + (size_t)row * DD + c4 * 4);
            *(uint2*)(sAp + row * 68 + 2 * c4) =
                make_uint2(packbf(a.x, a.y), packbf(a.z, a.w));
        }
        if (tid < 32)
            *(float4*)(sU + tid * 4) =
                *(const float4*)(g_u + ((size_t)b * NN + soff + s) * DD + tid * 4);
    }
    __syncthreads();

    // ---- per-warp tiling ----
    const int w    = tid >> 5;
    const int lane = tid & 31;
    const int wm   = w & 1;          // 0..1  (32 dst rows each)
    const int wn   = w >> 1;         // 0..3  (32 cols each)
    const int g    = lane >> 2;
    const int tig  = lane & 3;

    // ---- hoist ALL B fragments into registers (loop-invariant) ----
    uint32_t bB[8][4][2];
    #pragma unroll
    for (int ks = 0; ks < 8; ks++)
        #pragma unroll
        for (int nt = 0; nt < 4; nt++) {
            const int n = wn * 32 + nt * 8 + g;
            bB[ks][nt][0] = sWp[(ks * 8 + tig) * 136 + n];
            bB[ks][nt][1] = sWp[(ks * 8 + tig + 4) * 136 + n];
        }

    // ldmatrix per-lane addressing: quad = lane>>3 selects (m8-half, k8-half)
    const int quad  = lane >> 3;
    const int r8    = lane & 7;
    const int rowL  = wm * 32 + (quad & 1) * 8 + r8;  // + mt*16
    const int koffL = (quad >> 1) * 4;                // pair offset for k8-15
    const uint32_t aAddr0 = smem_u32(sAp) + (uint32_t)(rowL * 68 + koffL) * 4u;

    float agg[2][4][4];
    #pragma unroll
    for (int mt = 0; mt < 2; mt++)
        #pragma unroll
        for (int nt = 0; nt < 4; nt++)
            #pragma unroll
            for (int r = 0; r < 4; r++) agg[mt][nt][r] = 0.f;

    const int myrow = tid >> 5;          // staging rows (tid>>5) + 8*j
    const int myc4  = tid & 31;

    for (int i = 0; i < iters; i++) {
        const int p = i & 1;
        const bool have_next = (i + 1 < iters);
        const float* ebn = edge_attr +
            ((size_t)b * EE + ebase + (size_t)(s_begin + i + 1) * n_dst + d0) * DD;
        uint32_t* sAn = sAp + (p ^ 1) * 4352;

        // prefetch u(next) + first half of A(next): rows 0..31
        float4 rU;
        float4 rA[4];
        if (have_next) {
            if (tid < 32)
                rU = *(const float4*)(g_u +
                        ((size_t)b * NN + soff + s_begin + i + 1) * DD + tid * 4);
            #pragma unroll
            for (int j = 0; j < 4; j++) {
                const int row = myrow + 8 * j;
                if (d0 + row < n_dst)
                    rA[j] = *(const float4*)(ebn + (size_t)row * DD + myc4 * 4);
                else
                    rA[j] = make_float4(0.f, 0.f, 0.f, 0.f);
            }
        }

        float acc[2][4][4];
        #pragma unroll
        for (int mt = 0; mt < 2; mt++)
            #pragma unroll
            for (int nt = 0; nt < 4; nt++)
                #pragma unroll
                for (int r = 0; r < 4; r++) acc[mt][nt][r] = 0.f;

        const uint32_t aBase = aAddr0 + (uint32_t)p * (4352u * 4u);

        // ---- mma first half: ks 0..3 ----
        #pragma unroll
        for (int ks = 0; ks < 4; ks++) {
            #pragma unroll
            for (int mt = 0; mt < 2; mt++) {
                uint32_t a0, a1, a2, a3;
                ldsm_x4(a0, a1, a2, a3, aBase + (uint32_t)(mt * 16 * 68 + ks * 8) * 4u);
                #pragma unroll
                for (int nt = 0; nt < 4; nt++)
                    mma16(acc[mt][nt][0], acc[mt][nt][1], acc[mt][nt][2], acc[mt][nt][3],
                          a0, a1, a2, a3, bB[ks][nt][0], bB[ks][nt][1]);
            }
        }

        // issue second-half loads, then store first half into buffer p^1
        if (have_next) {
            float4 rB[4];
            #pragma unroll
            for (int j = 0; j < 4; j++) {
                const int row = 32 + myrow + 8 * j;
                if (d0 + row < n_dst)
                    rB[j] = *(const float4*)(ebn + (size_t)row * DD + myc4 * 4);
                else
                    rB[j] = make_float4(0.f, 0.f, 0.f, 0.f);
            }
            #pragma unroll
            for (int j = 0; j < 4; j++) {
                const int row = myrow + 8 * j;
                *(uint2*)(sAn + row * 68 + 2 * myc4) =
                    make_uint2(packbf(rA[j].x, rA[j].y), packbf(rA[j].z, rA[j].w));
                rA[j] = rB[j];
            }
        }

        // ---- mma second half: ks 4..7 ----
        #pragma unroll
        for (int ks = 4; ks < 8; ks++) {
            #pragma unroll
            for (int mt = 0; mt < 2; mt++) {
                uint32_t a0, a1, a2, a3;
                ldsm_x4(a0, a1, a2, a3, aBase + (uint32_t)(mt * 16 * 68 + ks * 8) * 4u);
                #pragma unroll
                for (int nt = 0; nt < 4; nt++)
                    mma16(acc[mt][nt][0], acc[mt][nt][1], acc[mt][nt][2], acc[mt][nt][3],
                          a0, a1, a2, a3, bB[ks][nt][0], bB[ks][nt][1]);
            }
        }

        // store second half of next A + u(next)
        if (have_next) {
            #pragma unroll
            for (int j = 0; j < 4; j++) {
                const int row = 32 + myrow + 8 * j;
                *(uint2*)(sAn + row * 68 + 2 * myc4) =
                    make_uint2(packbf(rA[j].x, rA[j].y), packbf(rA[j].z, rA[j].w));
            }
            if (tid < 32)
                *(float4*)(sU + (p ^ 1) * 128 + tid * 4) = rU;
        }

        // ---- epilogue: agg += relu(acc + u + v) ----
        const float* sUp = sU + p * 128;
        #pragma unroll
        for (int nt = 0; nt < 4; nt++) {
            const int col = wn * 32 + nt * 8 + 2 * tig;
            const float2 uu = *(const float2*)(sUp + col);
            #pragma unroll
            for (int mt = 0; mt < 2; mt++) {
                const int r0 = wm * 32 + mt * 16 + g;
                const float2 v0 = *(const float2*)(sV + r0 * 132 + col);
                const float2 v1 = *(const float2*)(sV + (r0 + 8) * 132 + col);
                agg[mt][nt][0] += fmaxf(acc[mt][nt][0] + uu.x + v0.x, 0.f);
                agg[mt][nt][1] += fmaxf(acc[mt][nt][1] + uu.y + v0.y, 0.f);
                agg[mt][nt][2] += fmaxf(acc[mt][nt][2] + uu.x + v1.x, 0.f);
                agg[mt][nt][3] += fmaxf(acc[mt][nt][3] + uu.y + v1.y, 0.f);
            }
        }
        __syncthreads();
    }

    // ---- store partial agg (scaled) into this chunk's buffer ----
    const float scale = 1.f / (float)n_src;
    float* aggbuf = g_agg + (size_t)chunk * AGG_STRIDE;
    #pragma unroll
    for (int mt = 0; mt < 2; mt++) {
        const int rloc = wm * 32 + mt * 16 + g;
        #pragma unroll
        for (int nt = 0; nt < 4; nt++) {
            const int col = wn * 32 + nt * 8 + 2 * tig;
            const int dg0 = d0 + rloc;
            const int dg1 = dg0 + 8;
            if (dg0 < n_dst)
                *(float2*)(aggbuf + ((size_t)b * NN + doff + dg0) * DD + col) =
                    make_float2(agg[mt][nt][0] * scale, agg[mt][nt][1] * scale);
            if (dg1 < n_dst)
                *(float2*)(aggbuf + ((size_t)b * NN + doff + dg1) * DD + col) =
                    make_float2(agg[mt][nt][2] * scale, agg[mt][nt][3] * scale);
        }
    }
}

// ---------------------------------------------------------------------------
// fused self+uv kernel: 8 rows/CTA, 916 CTAs.
//   if wself: x_new = relu(x @ Wself + b_self + sum_c agg[c]); write g_x
//   if wnext: u = x_new @ Wsrc ; v = x_new @ Wdst + b_msg  (next layer)
// ---------------------------------------------------------------------------
__global__ __launch_bounds__(128) void self_uv_kernel(const float* __restrict__ xin,
                                                      const float* __restrict__ wself,
                                                      const float* __restrict__ bself,
                                                      const float* __restrict__ wnext,
                                                      const float* __restrict__ bnext)
{
    __shared__ float xs[8][128];
    __shared__ float xn[8][128];
    const int t    = threadIdx.x;
    const int row0 = blockIdx.x * 8;

    const float* x = (xin != nullptr) ? xin : g_x;

    {
        const float4* src = (const float4*)(x + (size_t)row0 * DD);
        float4* dst = (float4*)&xs[0][0];
        dst[t]       = src[t];
        dst[t + 128] = src[t + 128];
    }
    __syncthreads();

    if (wself != nullptr) {
        float acc[8];
        #pragma unroll
        for (int r = 0; r < 8; r++) acc[r] = 0.f;
        #pragma unroll 8
        for (int k = 0; k < 128; k++) {
            const float w = __ldg(wself + k * 128 + t);
            #pragma unroll
            for (int r = 0; r < 8; r++) acc[r] += xs[r][k] * w;
        }
        const float bias = bself[t];
        #pragma unroll
        for (int r = 0; r < 8; r++) {
            const int row = row0 + r;
            const int n   = row % NN;
            float a = 0.f;
            if (n >= 64) {
                const size_t o = (size_t)row * DD + t;
                a = g_agg[o] + g_agg[AGG_STRIDE + o]
                  + g_agg[2 * (size_t)AGG_STRIDE + o] + g_agg[3 * (size_t)AGG_STRIDE + o];
            }
            const float xv = fmaxf(acc[r] + bias + a, 0.f);
            g_x[(size_t)row * DD + t] = xv;
            xn[r][t] = xv;
        }
    } else {
        #pragma unroll
        for (int r = 0; r < 8; r++) xn[r][t] = xs[r][t];
    }
    __syncthreads();

    if (wnext != nullptr) {
        float au[8], av[8];
        #pragma unroll
        for (int r = 0; r < 8; r++) { au[r] = 0.f; av[r] = 0.f; }
        #pragma unroll 4
        for (int k = 0; k < 128; k++) {
            const float wu = __ldg(wnext + k * 128 + t);
            const float wv = __ldg(wnext + (128 + k) * 128 + t);
            #pragma unroll
            for (int r = 0; r < 8; r++) {
                const float xv = xn[r][k];
                au[r] += xv * wu;
                av[r] += xv * wv;
            }
        }
        const float bias = bnext[t];
        #pragma unroll
        for (int r = 0; r < 8; r++) {
            const size_t o = (size_t)(row0 + r) * DD + t;
            g_u[o] = au[r];
            g_v[o] = av[r] + bias;
        }
    }
}

// ---------------------------------------------------------------------------
// head kernel: per batch b -> mean over nodes, 2x relu MLP, final [128x10]
// ---------------------------------------------------------------------------
__global__ __launch_bounds__(128) void head_kernel(const float* __restrict__ w1,
                                                   const float* __restrict__ b1,
                                                   const float* __restrict__ w2,
                                                   const float* __restrict__ b2,
                                                   const float* __restrict__ w3,
                                                   const float* __restrict__ b3,
                                                   float* __restrict__ out)
{
    __shared__ float g[128];
    __shared__ float h[128];
    const int b = blockIdx.x;
    const int t = threadIdx.x;

    float s = 0.f;
    const float* xb = g_x + (size_t)b * NN * DD;
    for (int n = 0; n < NN; n++) s += xb[(size_t)n * DD + t];
    g[t] = s * (1.f / (float)NN);
    __syncthreads();

    float acc = 0.f;
    #pragma unroll 4
    for (int k = 0; k < 128; k++) acc += g[k] * __ldg(w1 + k * 128 + t);
    h[t] = fmaxf(acc + b1[t], 0.f);
    __syncthreads();

    acc = 0.f;
    #pragma unroll 4
    for (int k = 0; k < 128; k++) acc += h[k] * __ldg(w2 + k * 128 + t);
    __syncthreads();
    g[t] = fmaxf(acc + b2[t], 0.f);
    __syncthreads();

    if (t < 10) {
        float o = b3[t];
        for (int k = 0; k < 128; k++) o += g[k] * __ldg(w3 + k * 10 + t);
        out[b * 10 + t] = o;
    }
}

// ---------------------------------------------------------------------------
// launch
// ---------------------------------------------------------------------------
extern "C" void kernel_launch(void* const* d_in, const int* in_sizes, int n_in,
                              void* d_out, int out_size)
{
    (void)in_sizes; (void)n_in; (void)out_size;
    const float* node_features = (const float*)d_in[0];
    const float* edge_attr     = (const float*)d_in[1];
    const float* w_msg         = (const float*)d_in[2];
    const float* b_msg         = (const float*)d_in[3];
    const float* w_self        = (const float*)d_in[4];
    const float* b_self        = (const float*)d_in[5];
    const float* w1            = (const float*)d_in[6];
    const float* b1            = (const float*)d_in[7];
    const float* w2            = (const float*)d_in[8];
    const float* b2            = (const float*)d_in[9];
    const float* w3            = (const float*)d_in[10];
    const float* b3            = (const float*)d_in[11];
    float* out = (float*)d_out;

    cudaFuncSetAttribute(edge_kernel, cudaFuncAttributeMaxDynamicSharedMemorySize,
                         EDGE_SMEM_BYTES);

    // layer-0 u,v (pure-uv mode)
    self_uv_kernel<<<916, 128>>>(node_features, nullptr, nullptr, w_msg, b_msg);

    for (int l = 0; l < 3; l++) {
        const float* wl  = w_msg + (size_t)l * 384 * 128;
        edge_kernel<<<448, 256, EDGE_SMEM_BYTES>>>(edge_attr, wl);

        const float* xin = (l == 0) ? node_features : nullptr;
        const float* wn  = (l < 2) ? w_msg + (size_t)(l + 1) * 384 * 128 : nullptr;
        const float* bn  = (l < 2) ? b_msg + (size_t)(l + 1) * 128 : nullptr;
        self_uv_kernel<<<916, 128>>>(xin, w_self + (size_t)l * 128 * 128,
                                     b_self + (size_t)l * 128, wn, bn);
    }
    head_kernel<<<16, 128>>>(w1, b1, w2, b2, w3, b3, out);
}

// round 7
// speedup vs baseline: 8.6573x; 1.1162x over previous
#include <cuda_runtime.h>
#include <cuda_bf16.h>
#include <cstdint>
#include <cstddef>

#define BB 16
#define NN 458
#define DD 128
#define EE 42240
#define AGG_STRIDE (BB * NN * DD)

// ---------------------------------------------------------------------------
// Scratch (device globals; no allocation allowed)
// ---------------------------------------------------------------------------
__device__ float g_x  [BB * NN * DD];        // current node features
__device__ float g_u  [BB * NN * DD];        // x @ W_src
__device__ float g_v  [BB * NN * DD];        // x @ W_dst + b_msg
__device__ float g_agg[4 * BB * NN * DD];    // four partial agg buffers (src chunks)
__device__ uint4 g_ebf[BB * EE * 16];        // edge_attr prepacked bf16x2 (173 MB)

// ---------------------------------------------------------------------------
// helpers
// ---------------------------------------------------------------------------
__device__ __forceinline__ uint32_t packbf(float lo, float hi) {
    uint32_t r;
    asm("cvt.rn.bf16x2.f32 %0, %1, %2;" : "=r"(r) : "f"(hi), "f"(lo));
    return r;
}

__device__ __forceinline__ uint32_t smem_u32(const void* p) {
    uint32_t a;
    asm("{ .reg .u64 t; cvta.to.shared.u64 t, %1; cvt.u32.u64 %0, t; }"
        : "=r"(a) : "l"(p));
    return a;
}

__device__ __forceinline__ void mma16(float& c0, float& c1, float& c2, float& c3,
                                      uint32_t a0, uint32_t a1, uint32_t a2, uint32_t a3,
                                      uint32_t b0, uint32_t b1) {
    asm volatile(
        "mma.sync.aligned.m16n8k16.row.col.f32.bf16.bf16.f32 "
        "{%0,%1,%2,%3},{%4,%5,%6,%7},{%8,%9},{%0,%1,%2,%3};"
        : "+f"(c0), "+f"(c1), "+f"(c2), "+f"(c3)
        : "r"(a0), "r"(a1), "r"(a2), "r"(a3), "r"(b0), "r"(b1));
}

__device__ __forceinline__ void ldsm_x4(uint32_t& r0, uint32_t& r1, uint32_t& r2,
                                        uint32_t& r3, uint32_t addr) {
    asm volatile("ldmatrix.sync.aligned.m8n8.x4.shared.b16 {%0,%1,%2,%3}, [%4];"
                 : "=r"(r0), "=r"(r1), "=r"(r2), "=r"(r3) : "r"(addr));
}

__device__ __forceinline__ void cp16(uint32_t daddr, const void* gptr, uint32_t srcsize) {
    asm volatile("cp.async.cg.shared.global [%0], [%1], 16, %2;"
                 :: "r"(daddr), "l"(gptr), "r"(srcsize) : "memory");
}

// ---------------------------------------------------------------------------
// prepack kernel: edge_attr fp32 -> bf16x2 packed (one-time per launch)
// ---------------------------------------------------------------------------
__global__ __launch_bounds__(256) void prepack_kernel(const float* __restrict__ ea)
{
    const size_t i = (size_t)blockIdx.x * 256 + threadIdx.x;  // uint4 index
    const float4 f0 = *(const float4*)(ea + i * 8);
    const float4 f1 = *(const float4*)(ea + i * 8 + 4);
    g_ebf[i] = make_uint4(packbf(f0.x, f0.y), packbf(f0.z, f0.w),
                          packbf(f1.x, f1.y), packbf(f1.z, f1.w));
}

// ---------------------------------------------------------------------------
// edge kernel: 512 threads, m-split 4 x n-split 4, cp.async double buffering.
// CTA = (batch, block, 64-dst tile, 1/4-src chunk). Per iter (one src s):
//   acc = Etile(s, d0..d0+63) @ Wedge   (m16n8k16 bf16, fp32 accum)
//   agg += relu(acc + u[s] + v[d])
// smem words: sWp [64][136] bf16x2, sA [2][64][68] bf16x2, sV [64][132] f32,
//             sU [2][128] f32
// ---------------------------------------------------------------------------
#define EW_SW 0
#define EW_SA 8704
#define EW_SV (EW_SA + 2 * 4352)
#define EW_SU (EW_SV + 64 * 132)
#define EDGE_SMEM_WORDS (EW_SU + 2 * 128)
#define EDGE_SMEM_BYTES (EDGE_SMEM_WORDS * 4)

__global__ __launch_bounds__(512, 1) void edge_kernel(const float* __restrict__ wl)
{
    extern __shared__ uint32_t smw[];
    uint32_t* sWp = smw + EW_SW;
    uint32_t* sAp = smw + EW_SA;
    float* sV = (float*)(smw + EW_SV);
    float* sU = (float*)(smw + EW_SU);
    const uint32_t sb = smem_u32(smw);

    const int tid = threadIdx.x;
    const int bx  = blockIdx.x;
    const int b   = bx / 28;
    const int it  = bx % 28;

    int lb, dtile, chunk;
    if      (it < 8)  { lb = 0; dtile = it >> 2;        chunk = it & 3; }
    else if (it < 16) { lb = 1; dtile = (it - 8) >> 2;  chunk = it & 3; }
    else if (it < 24) { lb = 2; dtile = (it - 16) >> 2; chunk = it & 3; }
    else              { lb = 3; dtile = 0;              chunk = it - 24; }

    const int nsrc_a[4] = {64, 128, 128, 128};
    const int ndst_a[4] = {128, 128, 128, 10};
    const int eb_a  [4] = {0, 8192, 24576, 40960};
    const int so_a  [4] = {0, 64, 192, 320};
    const int do_a  [4] = {64, 192, 320, 448};

    const int n_src = nsrc_a[lb];
    const int n_dst = ndst_a[lb];
    const int ebase = eb_a[lb];
    const int soff  = so_a[lb];
    const int doff  = do_a[lb];
    const int d0    = dtile * 64;

    const int iters   = n_src >> 2;
    const int s_begin = chunk * iters;

    // ---- async stagers ----
    auto stageA_async = [&](int buf, int s) {
        const uint32_t dbase = sb + (EW_SA + buf * 4352) * 4;
        #pragma unroll
        for (int j = 0; j < 2; j++) {
            const int idx = tid + 512 * j;
            const int row = idx >> 4, c = idx & 15;
            const bool ok = (d0 + row < n_dst);
            const size_t e = (size_t)b * EE + ebase +
                             (ok ? ((size_t)s * n_dst + d0 + row) : 0);
            cp16(dbase + (uint32_t)(row * 68 + c * 4) * 4u,
                 g_ebf + e * 16 + c, ok ? 16u : 0u);
        }
    };
    auto stageU_async = [&](int slot, int s) {
        if (tid < 32)
            cp16(sb + (EW_SU + slot * 128 + tid * 4) * 4u,
                 g_u + ((size_t)b * NN + soff + s) * DD + tid * 4, 16u);
    };

    // ---- prologue: buffer 0 via cp.async; sW / sV via normal stores ----
    stageA_async(0, s_begin);
    stageU_async(0, s_begin);
    asm volatile("cp.async.commit_group;" ::: "memory");

    {
        const float* wedge = wl + 256 * 128;
        for (int i = tid; i < 8192; i += 512) {
            const int kp = i >> 7, n = i & 127;
            sWp[kp * 136 + n] = packbf(wedge[(2 * kp) * 128 + n],
                                       wedge[(2 * kp + 1) * 128 + n]);
        }
    }
    for (int i = tid; i < 2048; i += 512) {
        const int row = i >> 5, c4 = i & 31;
        float4 v4 = make_float4(0.f, 0.f, 0.f, 0.f);
        if (d0 + row < n_dst)
            v4 = *(const float4*)(g_v + ((size_t)b * NN + doff + d0 + row) * DD + c4 * 4);
        *(float4*)(sV + row * 132 + c4 * 4) = v4;
    }
    asm volatile("cp.async.wait_group 0;" ::: "memory");
    __syncthreads();

    // ---- per-warp tiling: m-split 4 (16 rows), n-split 4 (32 cols) ----
    const int w    = tid >> 5;
    const int lane = tid & 31;
    const int wm   = w & 3;
    const int wn   = w >> 2;
    const int g    = lane >> 2;
    const int tig  = lane & 3;

    // hoist all B fragments (loop-invariant)
    uint32_t bB[8][4][2];
    #pragma unroll
    for (int ks = 0; ks < 8; ks++)
        #pragma unroll
        for (int nt = 0; nt < 4; nt++) {
            const int n = wn * 32 + nt * 8 + g;
            bB[ks][nt][0] = sWp[(ks * 8 + tig) * 136 + n];
            bB[ks][nt][1] = sWp[(ks * 8 + tig + 4) * 136 + n];
        }

    // ldmatrix addressing
    const int quad  = lane >> 3;
    const int r8    = lane & 7;
    const int rowL  = wm * 16 + (quad & 1) * 8 + r8;
    const int koffL = (quad >> 1) * 4;
    const uint32_t aAddr0 = sb + (EW_SA + rowL * 68 + koffL) * 4u;

    float agg[4][4];
    #pragma unroll
    for (int nt = 0; nt < 4; nt++)
        #pragma unroll
        for (int r = 0; r < 4; r++) agg[nt][r] = 0.f;

    for (int i = 0; i < iters; i++) {
        const int p = i & 1;
        const bool have_next = (i + 1 < iters);

        if (have_next) {
            stageA_async(p ^ 1, s_begin + i + 1);
            stageU_async(p ^ 1, s_begin + i + 1);
            asm volatile("cp.async.commit_group;" ::: "memory");
        }

        float acc[4][4];
        #pragma unroll
        for (int nt = 0; nt < 4; nt++)
            #pragma unroll
            for (int r = 0; r < 4; r++) acc[nt][r] = 0.f;

        const uint32_t aBase = aAddr0 + (uint32_t)p * (4352u * 4u);
        #pragma unroll
        for (int ks = 0; ks < 8; ks++) {
            uint32_t a0, a1, a2, a3;
            ldsm_x4(a0, a1, a2, a3, aBase + (uint32_t)ks * 32u);
            #pragma unroll
            for (int nt = 0; nt < 4; nt++)
                mma16(acc[nt][0], acc[nt][1], acc[nt][2], acc[nt][3],
                      a0, a1, a2, a3, bB[ks][nt][0], bB[ks][nt][1]);
        }

        // epilogue: agg += relu(acc + u + v)
        const float* sUp = sU + p * 128;
        const int r0 = wm * 16 + g;
        #pragma unroll
        for (int nt = 0; nt < 4; nt++) {
            const int col = wn * 32 + nt * 8 + 2 * tig;
            const float2 uu = *(const float2*)(sUp + col);
            const float2 v0 = *(const float2*)(sV + r0 * 132 + col);
            const float2 v1 = *(const float2*)(sV + (r0 + 8) * 132 + col);
            agg[nt][0] += fmaxf(acc[nt][0] + uu.x + v0.x, 0.f);
            agg[nt][1] += fmaxf(acc[nt][1] + uu.y + v0.y, 0.f);
            agg[nt][2] += fmaxf(acc[nt][2] + uu.x + v1.x, 0.f);
            agg[nt][3] += fmaxf(acc[nt][3] + uu.y + v1.y, 0.f);
        }

        if (have_next)
            asm volatile("cp.async.wait_group 0;" ::: "memory");
        __syncthreads();
    }

    // ---- store partial agg (scaled) into this chunk's buffer ----
    const float scale = 1.f / (float)n_src;
    float* aggbuf = g_agg + (size_t)chunk * AGG_STRIDE;
    const int dg0 = d0 + wm * 16 + g;
    const int dg1 = dg0 + 8;
    #pragma unroll
    for (int nt = 0; nt < 4; nt++) {
        const int col = wn * 32 + nt * 8 + 2 * tig;
        if (dg0 < n_dst)
            *(float2*)(aggbuf + ((size_t)b * NN + doff + dg0) * DD + col) =
                make_float2(agg[nt][0] * scale, agg[nt][1] * scale);
        if (dg1 < n_dst)
            *(float2*)(aggbuf + ((size_t)b * NN + doff + dg1) * DD + col) =
                make_float2(agg[nt][2] * scale, agg[nt][3] * scale);
    }
}

// ---------------------------------------------------------------------------
// fused self+uv kernel, 256 threads (k-split 2), 8 rows/CTA, 916 CTAs.
//   if wself: x_new = relu(x @ Wself + b_self + sum_c agg[c]); write g_x
//   if wnext: u = x_new @ Wsrc ; v = x_new @ Wdst + b_msg
// ---------------------------------------------------------------------------
__global__ __launch_bounds__(256) void self_uv_kernel(const float* __restrict__ xin,
                                                      const float* __restrict__ wself,
                                                      const float* __restrict__ bself,
                                                      const float* __restrict__ wnext,
                                                      const float* __restrict__ bnext)
{
    __shared__ float xs[8][128];
    __shared__ float xn[8][128];
    __shared__ float sred[2][8][128];
    const int tid  = threadIdx.x;
    const int t    = tid & 127;
    const int kh   = tid >> 7;
    const int row0 = blockIdx.x * 8;

    const float* x = (xin != nullptr) ? xin : g_x;

    ((float4*)xs)[tid] = ((const float4*)(x + (size_t)row0 * DD))[tid];
    __syncthreads();

    const int k0 = kh * 64;

    if (wself != nullptr) {
        float acc[8];
        #pragma unroll
        for (int r = 0; r < 8; r++) acc[r] = 0.f;
        #pragma unroll 8
        for (int kk = 0; kk < 64; kk++) {
            const int k = k0 + kk;
            const float w = __ldg(wself + k * 128 + t);
            #pragma unroll
            for (int r = 0; r < 8; r++) acc[r] += xs[r][k] * w;
        }
        if (kh == 1) {
            #pragma unroll
            for (int r = 0; r < 8; r++) sred[0][r][t] = acc[r];
        }
        __syncthreads();
        if (kh == 0) {
            const float bias = bself[t];
            #pragma unroll
            for (int r = 0; r < 8; r++) {
                const int row = row0 + r;
                const int n   = row % NN;
                float a = 0.f;
                if (n >= 64) {
                    const size_t o = (size_t)row * DD + t;
                    a = g_agg[o] + g_agg[AGG_STRIDE + o]
                      + g_agg[2 * (size_t)AGG_STRIDE + o]
                      + g_agg[3 * (size_t)AGG_STRIDE + o];
                }
                const float xv = fmaxf(acc[r] + sred[0][r][t] + bias + a, 0.f);
                g_x[(size_t)row * DD + t] = xv;
                xn[r][t] = xv;
            }
        }
        __syncthreads();
    } else {
        if (kh == 0) {
            #pragma unroll
            for (int r = 0; r < 8; r++) xn[r][t] = xs[r][t];
        }
        __syncthreads();
    }

    if (wnext != nullptr) {
        float au[8], av[8];
        #pragma unroll
        for (int r = 0; r < 8; r++) { au[r] = 0.f; av[r] = 0.f; }
        #pragma unroll 4
        for (int kk = 0; kk < 64; kk++) {
            const int k = k0 + kk;
            const float wu = __ldg(wnext + k * 128 + t);
            const float wv = __ldg(wnext + (128 + k) * 128 + t);
            #pragma unroll
            for (int r = 0; r < 8; r++) {
                const float xv = xn[r][k];
                au[r] += xv * wu;
                av[r] += xv * wv;
            }
        }
        if (kh == 1) {
            #pragma unroll
            for (int r = 0; r < 8; r++) { sred[0][r][t] = au[r]; sred[1][r][t] = av[r]; }
        }
        __syncthreads();
        if (kh == 0) {
            const float bias = bnext[t];
            #pragma unroll
            for (int r = 0; r < 8; r++) {
                const size_t o = (size_t)(row0 + r) * DD + t;
                g_u[o] = au[r] + sred[0][r][t];
                g_v[o] = av[r] + sred[1][r][t] + bias;
            }
        }
    }
}

// ---------------------------------------------------------------------------
// head kernel
// ---------------------------------------------------------------------------
__global__ __launch_bounds__(128) void head_kernel(const float* __restrict__ w1,
                                                   const float* __restrict__ b1,
                                                   const float* __restrict__ w2,
                                                   const float* __restrict__ b2,
                                                   const float* __restrict__ w3,
                                                   const float* __restrict__ b3,
                                                   float* __restrict__ out)
{
    __shared__ float g[128];
    __shared__ float h[128];
    const int b = blockIdx.x;
    const int t = threadIdx.x;

    float s = 0.f;
    const float* xb = g_x + (size_t)b * NN * DD;
    for (int n = 0; n < NN; n++) s += xb[(size_t)n * DD + t];
    g[t] = s * (1.f / (float)NN);
    __syncthreads();

    float acc = 0.f;
    #pragma unroll 4
    for (int k = 0; k < 128; k++) acc += g[k] * __ldg(w1 + k * 128 + t);
    h[t] = fmaxf(acc + b1[t], 0.f);
    __syncthreads();

    acc = 0.f;
    #pragma unroll 4
    for (int k = 0; k < 128; k++) acc += h[k] * __ldg(w2 + k * 128 + t);
    __syncthreads();
    g[t] = fmaxf(acc + b2[t], 0.f);
    __syncthreads();

    if (t < 10) {
        float o = b3[t];
        for (int k = 0; k < 128; k++) o += g[k] * __ldg(w3 + k * 10 + t);
        out[b * 10 + t] = o;
    }
}

// ---------------------------------------------------------------------------
// launch
// ---------------------------------------------------------------------------
extern "C" void kernel_launch(void* const* d_in, const int* in_sizes, int n_in,
                              void* d_out, int out_size)
{
    (void)in_sizes; (void)n_in; (void)out_size;
    const float* node_features = (const float*)d_in[0];
    const float* edge_attr     = (const float*)d_in[1];
    const float* w_msg         = (const float*)d_in[2];
    const float* b_msg         = (const float*)d_in[3];
    const float* w_self        = (const float*)d_in[4];
    const float* b_self        = (const float*)d_in[5];
    const float* w1            = (const float*)d_in[6];
    const float* b1            = (const float*)d_in[7];
    const float* w2            = (const float*)d_in[8];
    const float* b2            = (const float*)d_in[9];
    const float* w3            = (const float*)d_in[10];
    const float* b3            = (const float*)d_in[11];
    float* out = (float*)d_out;

    cudaFuncSetAttribute(edge_kernel, cudaFuncAttributeMaxDynamicSharedMemorySize,
                         EDGE_SMEM_BYTES);

    // one-time bf16 prepack of edge_attr (16*42240*16 uint4 total)
    prepack_kernel<<<42240, 256>>>(edge_attr);

    // layer-0 u,v (pure-uv mode)
    self_uv_kernel<<<916, 256>>>(node_features, nullptr, nullptr, w_msg, b_msg);

    for (int l = 0; l < 3; l++) {
        const float* wl = w_msg + (size_t)l * 384 * 128;
        edge_kernel<<<448, 512, EDGE_SMEM_BYTES>>>(wl);

        const float* xin = (l == 0) ? node_features : nullptr;
        const float* wn  = (l < 2) ? w_msg + (size_t)(l + 1) * 384 * 128 : nullptr;
        const float* bn  = (l < 2) ? b_msg + (size_t)(l + 1) * 128 : nullptr;
        self_uv_kernel<<<916, 256>>>(xin, w_self + (size_t)l * 128 * 128,
                                     b_self + (size_t)l * 128, wn, bn);
    }
    head_kernel<<<16, 128>>>(w1, b1, w2, b2, w3, b3, out);
}

// round 9
// speedup vs baseline: 9.1704x; 1.0593x over previous
#include <cuda_runtime.h>
#include <cuda_bf16.h>
#include <cstdint>
#include <cstddef>

#define BB 16
#define NN 458
#define DD 128
#define EE 42240
#define NROWS (BB * NN)              // 7328
#define AGG_STRIDE (BB * NN * DD)

// ---------------------------------------------------------------------------
// Scratch (device globals; no allocation allowed)
// ---------------------------------------------------------------------------
__device__ float g_x  [BB * NN * DD];        // current node features
__device__ float g_u  [BB * NN * DD];        // x @ W_src
__device__ float g_v  [BB * NN * DD];        // x @ W_dst + b_msg
__device__ float g_agg[4 * BB * NN * DD];    // four partial agg buffers
__device__ uint4 g_ebf[BB * EE * 16];        // edge_attr prepacked bf16x2

// ---------------------------------------------------------------------------
// helpers
// ---------------------------------------------------------------------------
__device__ __forceinline__ uint32_t packbf(float lo, float hi) {
    uint32_t r;
    asm("cvt.rn.bf16x2.f32 %0, %1, %2;" : "=r"(r) : "f"(hi), "f"(lo));
    return r;
}

__device__ __forceinline__ float to_tf32(float x) {
    uint32_t u;
    asm("cvt.rna.tf32.f32 %0, %1;" : "=r"(u) : "f"(x));
    return __uint_as_float(u);
}

__device__ __forceinline__ uint32_t smem_u32(const void* p) {
    uint32_t a;
    asm("{ .reg .u64 t; cvta.to.shared.u64 t, %1; cvt.u32.u64 %0, t; }"
        : "=r"(a) : "l"(p));
    return a;
}

__device__ __forceinline__ void mma16(float& c0, float& c1, float& c2, float& c3,
                                      uint32_t a0, uint32_t a1, uint32_t a2, uint32_t a3,
                                      uint32_t b0, uint32_t b1) {
    asm volatile(
        "mma.sync.aligned.m16n8k16.row.col.f32.bf16.bf16.f32 "
        "{%0,%1,%2,%3},{%4,%5,%6,%7},{%8,%9},{%0,%1,%2,%3};"
        : "+f"(c0), "+f"(c1), "+f"(c2), "+f"(c3)
        : "r"(a0), "r"(a1), "r"(a2), "r"(a3), "r"(b0), "r"(b1));
}

__device__ __forceinline__ void mma8(float& c0, float& c1, float& c2, float& c3,
                                     uint32_t a0, uint32_t a1, uint32_t a2, uint32_t a3,
                                     uint32_t b0, uint32_t b1) {
    asm volatile(
        "mma.sync.aligned.m16n8k8.row.col.f32.tf32.tf32.f32 "
        "{%0,%1,%2,%3},{%4,%5,%6,%7},{%8,%9},{%0,%1,%2,%3};"
        : "+f"(c0), "+f"(c1), "+f"(c2), "+f"(c3)
        : "r"(a0), "r"(a1), "r"(a2), "r"(a3), "r"(b0), "r"(b1));
}

__device__ __forceinline__ void ldsm_x4(uint32_t& r0, uint32_t& r1, uint32_t& r2,
                                        uint32_t& r3, uint32_t addr) {
    asm volatile("ldmatrix.sync.aligned.m8n8.x4.shared.b16 {%0,%1,%2,%3}, [%4];"
                 : "=r"(r0), "=r"(r1), "=r"(r2), "=r"(r3) : "r"(addr));
}

__device__ __forceinline__ void cp16(uint32_t daddr, const void* gptr, uint32_t srcsize) {
    asm volatile("cp.async.cg.shared.global [%0], [%1], 16, %2;"
                 :: "r"(daddr), "l"(gptr), "r"(srcsize) : "memory");
}

// ---------------------------------------------------------------------------
// prepack kernel: edge_attr fp32 -> bf16x2 packed
// ---------------------------------------------------------------------------
__global__ __launch_bounds__(256) void prepack_kernel(const float* __restrict__ ea)
{
    const size_t i = (size_t)blockIdx.x * 256 + threadIdx.x;
    const float4 f0 = *(const float4*)(ea + i * 8);
    const float4 f1 = *(const float4*)(ea + i * 8 + 4);
    g_ebf[i] = make_uint4(packbf(f0.x, f0.y), packbf(f0.z, f0.w),
                          packbf(f1.x, f1.y), packbf(f1.z, f1.w));
}

// ---------------------------------------------------------------------------
// edge kernel: 512 threads, m-split 4 x n-split 4, cp.async double buffering.
// Blocks 0..2: CTA = (batch, block, 64-dst tile, 1/4-src chunk), 1 src/iter.
// Block 3 (128 src x 10 dst): 1 CTA/batch, 4 srcs packed per 64-row tile
// (16 dst-rows each); warp-row group wm = src group, agg buffer = wm.
// ---------------------------------------------------------------------------
#define EW_SW 0
#define EW_SA 8704
#define EW_SV (EW_SA + 2 * 4352)
#define EW_SU (EW_SV + 64 * 132)
#define EDGE_SMEM_WORDS (EW_SU + 2 * 512)
#define EDGE_SMEM_BYTES (EDGE_SMEM_WORDS * 4)

__global__ __launch_bounds__(512, 1) void edge_kernel(const float* __restrict__ wl)
{
    extern __shared__ uint32_t smw[];
    uint32_t* sWp = smw + EW_SW;
    float* sV = (float*)(smw + EW_SV);
    float* sU = (float*)(smw + EW_SU);
    const uint32_t sb = smem_u32(smw);

    const int tid = threadIdx.x;
    const int bx  = blockIdx.x;
    const int b   = bx / 25;
    const int it  = bx % 25;

    int lb, dtile, chunk;
    if      (it < 8)  { lb = 0; dtile = it >> 2;        chunk = it & 3; }
    else if (it < 16) { lb = 1; dtile = (it - 8) >> 2;  chunk = it & 3; }
    else if (it < 24) { lb = 2; dtile = (it - 16) >> 2; chunk = it & 3; }
    else              { lb = 3; dtile = 0;              chunk = 0;      }

    const int nsrc_a[4] = {64, 128, 128, 128};
    const int ndst_a[4] = {128, 128, 128, 10};
    const int eb_a  [4] = {0, 8192, 24576, 40960};
    const int so_a  [4] = {0, 64, 192, 320};
    const int do_a  [4] = {64, 192, 320, 448};

    const int n_src = nsrc_a[lb];
    const int n_dst = ndst_a[lb];
    const int ebase = eb_a[lb];
    const int soff  = so_a[lb];
    const int doff  = do_a[lb];
    const int d0    = dtile * 64;

    const bool packed4 = (lb == 3);
    const int sshift = packed4 ? 4 : 6;
    const int rmask  = packed4 ? 15 : 63;
    const int sstep  = packed4 ? 4 : 1;
    const int nsrow  = packed4 ? 4 : 1;
    const int iters  = packed4 ? 32 : (n_src >> 2);
    const int s_begin = packed4 ? 0 : chunk * iters;

    auto stageA_async = [&](int buf, int s0) {
        const uint32_t dbase = sb + (EW_SA + buf * 4352) * 4;
        #pragma unroll
        for (int j = 0; j < 2; j++) {
            const int idx = tid + 512 * j;
            const int row = idx >> 4, c = idx & 15;
            const int dgl = row & rmask;
            const int s   = s0 + (row >> sshift);
            const bool ok = (d0 + dgl < n_dst);
            const size_t e = (size_t)b * EE + ebase +
                             (ok ? ((size_t)s * n_dst + d0 + dgl) : 0);
            cp16(dbase + (uint32_t)(row * 68 + c * 4) * 4u,
                 g_ebf + e * 16 + c, ok ? 16u : 0u);
        }
    };
    auto stageU_async = [&](int slot, int s0) {
        if (tid < 32 * nsrow) {
            const int sl = tid >> 5, c4 = tid & 31;
            cp16(sb + (EW_SU + slot * 512 + sl * 128 + c4 * 4) * 4u,
                 g_u + ((size_t)b * NN + soff + s0 + sl) * DD + c4 * 4, 16u);
        }
    };

    stageA_async(0, s_begin);
    stageU_async(0, s_begin);
    asm volatile("cp.async.commit_group;" ::: "memory");

    {
        const float* wedge = wl + 256 * 128;
        for (int i = tid; i < 8192; i += 512) {
            const int kp = i >> 7, n = i & 127;
            sWp[kp * 136 + n] = packbf(wedge[(2 * kp) * 128 + n],
                                       wedge[(2 * kp + 1) * 128 + n]);
        }
    }
    for (int i = tid; i < 2048; i += 512) {
        const int row = i >> 5, c4 = i & 31;
        const int dgl = row & rmask;
        float4 v4 = make_float4(0.f, 0.f, 0.f, 0.f);
        if (d0 + dgl < n_dst)
            v4 = *(const float4*)(g_v + ((size_t)b * NN + doff + d0 + dgl) * DD + c4 * 4);
        *(float4*)(sV + row * 132 + c4 * 4) = v4;
    }
    asm volatile("cp.async.wait_group 0;" ::: "memory");
    __syncthreads();

    const int w    = tid >> 5;
    const int lane = tid & 31;
    const int wm   = w & 3;
    const int wn   = w >> 2;
    const int g    = lane >> 2;
    const int tig  = lane & 3;

    uint32_t bB[8][4][2];
    #pragma unroll
    for (int ks = 0; ks < 8; ks++)
        #pragma unroll
        for (int nt = 0; nt < 4; nt++) {
            const int n = wn * 32 + nt * 8 + g;
            bB[ks][nt][0] = sWp[(ks * 8 + tig) * 136 + n];
            bB[ks][nt][1] = sWp[(ks * 8 + tig + 4) * 136 + n];
        }

    const int quad  = lane >> 3;
    const int r8    = lane & 7;
    const int rowL  = wm * 16 + (quad & 1) * 8 + r8;
    const int koffL = (quad >> 1) * 4;
    const uint32_t aAddr0 = sb + (EW_SA + rowL * 68 + koffL) * 4u;

    float agg[4][4];
    #pragma unroll
    for (int nt = 0; nt < 4; nt++)
        #pragma unroll
        for (int r = 0; r < 4; r++) agg[nt][r] = 0.f;

    for (int i = 0; i < iters; i++) {
        const int p = i & 1;
        const bool have_next = (i + 1 < iters);

        if (have_next) {
            stageA_async(p ^ 1, s_begin + (i + 1) * sstep);
            stageU_async(p ^ 1, s_begin + (i + 1) * sstep);
            asm volatile("cp.async.commit_group;" ::: "memory");
        }

        float acc[4][4];
        #pragma unroll
        for (int nt = 0; nt < 4; nt++)
            #pragma unroll
            for (int r = 0; r < 4; r++) acc[nt][r] = 0.f;

        const uint32_t aBase = aAddr0 + (uint32_t)p * (4352u * 4u);
        #pragma unroll
        for (int ks = 0; ks < 8; ks++) {
            uint32_t a0, a1, a2, a3;
            ldsm_x4(a0, a1, a2, a3, aBase + (uint32_t)ks * 32u);
            #pragma unroll
            for (int nt = 0; nt < 4; nt++)
                mma16(acc[nt][0], acc[nt][1], acc[nt][2], acc[nt][3],
                      a0, a1, a2, a3, bB[ks][nt][0], bB[ks][nt][1]);
        }

        const float* sUp = sU + p * 512 + (packed4 ? wm * 128 : 0);
        const int r0 = wm * 16 + g;
        #pragma unroll
        for (int nt = 0; nt < 4; nt++) {
            const int col = wn * 32 + nt * 8 + 2 * tig;
            const float2 uu = *(const float2*)(sUp + col);
            const float2 v0 = *(const float2*)(sV + r0 * 132 + col);
            const float2 v1 = *(const float2*)(sV + (r0 + 8) * 132 + col);
            agg[nt][0] += fmaxf(acc[nt][0] + uu.x + v0.x, 0.f);
            agg[nt][1] += fmaxf(acc[nt][1] + uu.y + v0.y, 0.f);
            agg[nt][2] += fmaxf(acc[nt][2] + uu.x + v1.x, 0.f);
            agg[nt][3] += fmaxf(acc[nt][3] + uu.y + v1.y, 0.f);
        }

        if (have_next)
            asm volatile("cp.async.wait_group 0;" ::: "memory");
        __syncthreads();
    }

    const float scale = 1.f / (float)n_src;
    const int chunkbuf = packed4 ? wm : chunk;
    float* aggbuf = g_agg + (size_t)chunkbuf * AGG_STRIDE;
    const int dg0 = d0 + ((wm * 16 + g) & rmask);
    const int dg1 = d0 + ((wm * 16 + g + 8) & rmask);
    #pragma unroll
    for (int nt = 0; nt < 4; nt++) {
        const int col = wn * 32 + nt * 8 + 2 * tig;
        if (dg0 < n_dst)
            *(float2*)(aggbuf + ((size_t)b * NN + doff + dg0) * DD + col) =
                make_float2(agg[nt][0] * scale, agg[nt][1] * scale);
        if (dg1 < n_dst)
            *(float2*)(aggbuf + ((size_t)b * NN + doff + dg1) * DD + col) =
                make_float2(agg[nt][2] * scale, agg[nt][3] * scale);
    }
}

// ---------------------------------------------------------------------------
// self_uv_tf32: 64-row tiles, 256 threads, tf32 tensor cores (fp32-grade
// precision for the chained node GEMMs). One reused W buffer, 3 phases:
//  1) x_new = relu(x@Wself + b + sum agg) -> g_x (fp32) + xn (tf32)
//  2) u = xn@Wsrc -> g_u
//  3) v = xn@Wdst + b_msg -> g_v
// ---------------------------------------------------------------------------
#define SU_XS 0
#define SU_XN 8448                   // 64*132
#define SU_W  16896
#define SU_WORDS (SU_W + 128 * 136)  // 34304 words = 137216 B
#define SU_SMEM_BYTES (SU_WORDS * 4)

__global__ __launch_bounds__(256, 1) void self_uv_tf32(const float* __restrict__ xin,
                                                       const float* __restrict__ wself,
                                                       const float* __restrict__ bself,
                                                       const float* __restrict__ wnext,
                                                       const float* __restrict__ bnext)
{
    extern __shared__ float smf[];
    float* xs = smf + SU_XS;
    float* xn = smf + SU_XN;
    float* sW = smf + SU_W;

    const int tid  = threadIdx.x;
    const int row0 = blockIdx.x * 64;
    const float* x = (xin != nullptr) ? xin : g_x;

    auto stageW = [&](const float* wsrc) {
        for (int i = tid; i < 4096; i += 256) {
            const int kr = i >> 5, c4 = i & 31;
            float4 wv = *(const float4*)(wsrc + kr * 128 + c4 * 4);
            wv.x = to_tf32(wv.x); wv.y = to_tf32(wv.y);
            wv.z = to_tf32(wv.z); wv.w = to_tf32(wv.w);
            *(float4*)(sW + kr * 136 + c4 * 4) = wv;
        }
    };

    // stage x tile (tf32) into xs (self mode) or xn (uv-only mode)
    {
        float* xt = (wself != nullptr) ? xs : xn;
        for (int i = tid; i < 2048; i += 256) {
            const int r = i >> 5, c4 = i & 31;
            const int row = row0 + r;
            float4 xv = make_float4(0.f, 0.f, 0.f, 0.f);
            if (row < NROWS)
                xv = *(const float4*)(x + (size_t)row * DD + c4 * 4);
            xv.x = to_tf32(xv.x); xv.y = to_tf32(xv.y);
            xv.z = to_tf32(xv.z); xv.w = to_tf32(xv.w);
            *(float4*)(xt + r * 132 + c4 * 4) = xv;
        }
    }
    if (wself != nullptr) stageW(wself);
    __syncthreads();

    // warp tiling: wm = w&3 (16 rows), wn = w>>2 (64 cols, 8 n-frags)
    const int w    = tid >> 5;
    const int lane = tid & 31;
    const int wm   = w & 3;
    const int wn   = w >> 2;
    const int g    = lane >> 2;
    const int tig  = lane & 3;
    const int rowg0 = row0 + wm * 16 + g;

    const uint32_t* sWu = (const uint32_t*)sW;

    auto gemm = [&](const float* A, float (&acc)[8][4]) {
        #pragma unroll
        for (int nt = 0; nt < 8; nt++)
            #pragma unroll
            for (int r = 0; r < 4; r++) acc[nt][r] = 0.f;
        const uint32_t* Au = (const uint32_t*)A;
        const int base0 = (wm * 16 + g) * 132;
        #pragma unroll
        for (int ks = 0; ks < 16; ks++) {
            const int kb = ks * 8;
            const uint32_t a0 = Au[base0 + kb + tig];
            const uint32_t a1 = Au[base0 + 8 * 132 + kb + tig];
            const uint32_t a2 = Au[base0 + kb + tig + 4];
            const uint32_t a3 = Au[base0 + 8 * 132 + kb + tig + 4];
            #pragma unroll
            for (int nt = 0; nt < 8; nt++) {
                const int n = wn * 64 + nt * 8 + g;
                const uint32_t b0 = sWu[(kb + tig) * 136 + n];
                const uint32_t b1 = sWu[(kb + tig + 4) * 136 + n];
                mma8(acc[nt][0], acc[nt][1], acc[nt][2], acc[nt][3],
                     a0, a1, a2, a3, b0, b1);
            }
        }
    };

    // ---------------- stage 1: x_new = relu(x@Wself + b + agg) ----------------
    if (wself != nullptr) {
        float acc[8][4];
        gemm(xs, acc);

        #pragma unroll
        for (int rr = 0; rr < 2; rr++) {
            const int row = rowg0 + rr * 8;
            const bool valid = (row < NROWS);
            const bool hasagg = valid && ((row % NN) >= 64);
            #pragma unroll
            for (int nt = 0; nt < 8; nt++) {
                const int col = wn * 64 + nt * 8 + 2 * tig;
                float c0 = acc[nt][rr * 2 + 0] + __ldg(bself + col);
                float c1 = acc[nt][rr * 2 + 1] + __ldg(bself + col + 1);
                if (hasagg) {
                    const size_t o = (size_t)row * DD + col;
                    #pragma unroll
                    for (int cb = 0; cb < 4; cb++) {
                        const float2 av = *(const float2*)(g_agg + (size_t)cb * AGG_STRIDE + o);
                        c0 += av.x; c1 += av.y;
                    }
                }
                c0 = fmaxf(c0, 0.f);
                c1 = fmaxf(c1, 0.f);
                if (valid)
                    *(float2*)(g_x + (size_t)row * DD + col) = make_float2(c0, c1);
                *(float2*)(xn + (wm * 16 + g + rr * 8) * 132 + col) =
                    make_float2(to_tf32(c0), to_tf32(c1));
            }
        }
        __syncthreads();
    }

    // ---------------- stage 2: u = xn@Wsrc ; v = xn@Wdst + bias ----------------
    if (wnext != nullptr) {
        #pragma unroll
        for (int pass = 0; pass < 2; pass++) {
            stageW(wnext + (size_t)pass * 128 * 128);
            __syncthreads();

            float acc[8][4];
            gemm(xn, acc);

            float* gout = (pass == 0) ? g_u : g_v;
            #pragma unroll
            for (int rr = 0; rr < 2; rr++) {
                const int row = rowg0 + rr * 8;
                if (row < NROWS) {
                    #pragma unroll
                    for (int nt = 0; nt < 8; nt++) {
                        const int col = wn * 64 + nt * 8 + 2 * tig;
                        float c0 = acc[nt][rr * 2 + 0];
                        float c1 = acc[nt][rr * 2 + 1];
                        if (pass == 1) {
                            c0 += __ldg(bnext + col);
                            c1 += __ldg(bnext + col + 1);
                        }
                        *(float2*)(gout + (size_t)row * DD + col) = make_float2(c0, c1);
                    }
                }
            }
            if (pass == 0) __syncthreads();
        }
    }
}

// ---------------------------------------------------------------------------
// head kernel
// ---------------------------------------------------------------------------
__global__ __launch_bounds__(128) void head_kernel(const float* __restrict__ w1,
                                                   const float* __restrict__ b1,
                                                   const float* __restrict__ w2,
                                                   const float* __restrict__ b2,
                                                   const float* __restrict__ w3,
                                                   const float* __restrict__ b3,
                                                   float* __restrict__ out)
{
    __shared__ float g[128];
    __shared__ float h[128];
    const int b = blockIdx.x;
    const int t = threadIdx.x;

    float s = 0.f;
    const float* xb = g_x + (size_t)b * NN * DD;
    for (int n = 0; n < NN; n++) s += xb[(size_t)n * DD + t];
    g[t] = s * (1.f / (float)NN);
    __syncthreads();

    float acc = 0.f;
    #pragma unroll 4
    for (int k = 0; k < 128; k++) acc += g[k] * __ldg(w1 + k * 128 + t);
    h[t] = fmaxf(acc + b1[t], 0.f);
    __syncthreads();

    acc = 0.f;
    #pragma unroll 4
    for (int k = 0; k < 128; k++) acc += h[k] * __ldg(w2 + k * 128 + t);
    __syncthreads();
    g[t] = fmaxf(acc + b2[t], 0.f);
    __syncthreads();

    if (t < 10) {
        float o = b3[t];
        for (int k = 0; k < 128; k++) o += g[k] * __ldg(w3 + k * 10 + t);
        out[b * 10 + t] = o;
    }
}

// ---------------------------------------------------------------------------
// launch
// ---------------------------------------------------------------------------
extern "C" void kernel_launch(void* const* d_in, const int* in_sizes, int n_in,
                              void* d_out, int out_size)
{
    (void)in_sizes; (void)n_in; (void)out_size;
    const float* node_features = (const float*)d_in[0];
    const float* edge_attr     = (const float*)d_in[1];
    const float* w_msg         = (const float*)d_in[2];
    const float* b_msg         = (const float*)d_in[3];
    const float* w_self        = (const float*)d_in[4];
    const float* b_self        = (const float*)d_in[5];
    const float* w1            = (const float*)d_in[6];
    const float* b1            = (const float*)d_in[7];
    const float* w2            = (const float*)d_in[8];
    const float* b2            = (const float*)d_in[9];
    const float* w3            = (const float*)d_in[10];
    const float* b3            = (const float*)d_in[11];
    float* out = (float*)d_out;

    cudaFuncSetAttribute(edge_kernel, cudaFuncAttributeMaxDynamicSharedMemorySize,
                         EDGE_SMEM_BYTES);
    cudaFuncSetAttribute(self_uv_tf32, cudaFuncAttributeMaxDynamicSharedMemorySize,
                         SU_SMEM_BYTES);

    prepack_kernel<<<42240, 256>>>(edge_attr);

    // layer-0 u,v (uv-only mode)
    self_uv_tf32<<<115, 256, SU_SMEM_BYTES>>>(node_features, nullptr, nullptr,
                                              w_msg, b_msg);

    for (int l = 0; l < 3; l++) {
        const float* wl = w_msg + (size_t)l * 384 * 128;
        edge_kernel<<<400, 512, EDGE_SMEM_BYTES>>>(wl);

        const float* xin = (l == 0) ? node_features : nullptr;
        const float* wn  = (l < 2) ? w_msg + (size_t)(l + 1) * 384 * 128 : nullptr;
        const float* bn  = (l < 2) ? b_msg + (size_t)(l + 1) * 128 : nullptr;
        self_uv_tf32<<<115, 256, SU_SMEM_BYTES>>>(xin, w_self + (size_t)l * 128 * 128,
                                                  b_self + (size_t)l * 128, wn, bn);
    }
    head_kernel<<<16, 128>>>(w1, b1, w2, b2, w3, b3, out);
}

// round 10
// speedup vs baseline: 9.6556x; 1.0529x over previous
#include <cuda_runtime.h>
#include <cuda_bf16.h>
#include <cstdint>
#include <cstddef>

#define BB 16
#define NN 458
#define DD 128
#define EE 42240
#define NROWS (BB * NN)              // 7328
#define AGG_STRIDE (BB * NN * DD)
#define N_ITEMS 672                  // 42 items/batch * 16 batches
#define EDGE_GRID 148

// ---------------------------------------------------------------------------
// Scratch (device globals; no allocation allowed)
// ---------------------------------------------------------------------------
__device__ float g_x  [BB * NN * DD];        // current node features
__device__ float g_u  [BB * NN * DD];        // x @ W_src
__device__ float g_v  [BB * NN * DD];        // x @ W_dst + b_msg
__device__ float g_agg[8 * BB * NN * DD];    // eight partial agg buffers
__device__ uint4 g_ebf[BB * EE * 16];        // edge_attr prepacked bf16x2

// ---------------------------------------------------------------------------
// helpers
// ---------------------------------------------------------------------------
__device__ __forceinline__ uint32_t packbf(float lo, float hi) {
    uint32_t r;
    asm("cvt.rn.bf16x2.f32 %0, %1, %2;" : "=r"(r) : "f"(hi), "f"(lo));
    return r;
}

__device__ __forceinline__ float to_tf32(float x) {
    uint32_t u;
    asm("cvt.rna.tf32.f32 %0, %1;" : "=r"(u) : "f"(x));
    return __uint_as_float(u);
}

__device__ __forceinline__ uint32_t smem_u32(const void* p) {
    uint32_t a;
    asm("{ .reg .u64 t; cvta.to.shared.u64 t, %1; cvt.u32.u64 %0, t; }"
        : "=r"(a) : "l"(p));
    return a;
}

__device__ __forceinline__ void mma16(float& c0, float& c1, float& c2, float& c3,
                                      uint32_t a0, uint32_t a1, uint32_t a2, uint32_t a3,
                                      uint32_t b0, uint32_t b1) {
    asm volatile(
        "mma.sync.aligned.m16n8k16.row.col.f32.bf16.bf16.f32 "
        "{%0,%1,%2,%3},{%4,%5,%6,%7},{%8,%9},{%0,%1,%2,%3};"
        : "+f"(c0), "+f"(c1), "+f"(c2), "+f"(c3)
        : "r"(a0), "r"(a1), "r"(a2), "r"(a3), "r"(b0), "r"(b1));
}

__device__ __forceinline__ void mma8(float& c0, float& c1, float& c2, float& c3,
                                     uint32_t a0, uint32_t a1, uint32_t a2, uint32_t a3,
                                     uint32_t b0, uint32_t b1) {
    asm volatile(
        "mma.sync.aligned.m16n8k8.row.col.f32.tf32.tf32.f32 "
        "{%0,%1,%2,%3},{%4,%5,%6,%7},{%8,%9},{%0,%1,%2,%3};"
        : "+f"(c0), "+f"(c1), "+f"(c2), "+f"(c3)
        : "r"(a0), "r"(a1), "r"(a2), "r"(a3), "r"(b0), "r"(b1));
}

__device__ __forceinline__ void ldsm_x4(uint32_t& r0, uint32_t& r1, uint32_t& r2,
                                        uint32_t& r3, uint32_t addr) {
    asm volatile("ldmatrix.sync.aligned.m8n8.x4.shared.b16 {%0,%1,%2,%3}, [%4];"
                 : "=r"(r0), "=r"(r1), "=r"(r2), "=r"(r3) : "r"(addr));
}

__device__ __forceinline__ void cp16(uint32_t daddr, const void* gptr, uint32_t srcsize) {
    asm volatile("cp.async.cg.shared.global [%0], [%1], 16, %2;"
                 :: "r"(daddr), "l"(gptr), "r"(srcsize) : "memory");
}

// ---------------------------------------------------------------------------
// prepack kernel: edge_attr fp32 -> bf16x2 packed
// ---------------------------------------------------------------------------
__global__ __launch_bounds__(256) void prepack_kernel(const float* __restrict__ ea)
{
    const size_t i = (size_t)blockIdx.x * 256 + threadIdx.x;
    const float4 f0 = *(const float4*)(ea + i * 8);
    const float4 f1 = *(const float4*)(ea + i * 8 + 4);
    g_ebf[i] = make_uint4(packbf(f0.x, f0.y), packbf(f0.z, f0.w),
                          packbf(f1.x, f1.y), packbf(f1.z, f1.w));
}

// ---------------------------------------------------------------------------
// persistent edge kernel: 148 CTAs, 512 threads, 672 uniform items (16 iters).
// item = (batch, block, 64-dst tile, 16-src chunk)  [block 3: 4-src packed]
// W_edge staged + B-fragments hoisted ONCE per CTA; triple-buffered cp.async.
// ---------------------------------------------------------------------------
#define EW_SW 0
#define EW_SA 8704                     // 3 x 4352 A buffers
#define EW_SV (EW_SA + 3 * 4352)       // V tile 64x132
#define EW_SU (EW_SV + 64 * 132)       // 3 slots x 512 floats
#define EDGE_SMEM_WORDS (EW_SU + 3 * 512)
#define EDGE_SMEM_BYTES (EDGE_SMEM_WORDS * 4)

__global__ __launch_bounds__(512, 1) void edge_kernel(const float* __restrict__ wl)
{
    extern __shared__ uint32_t smw[];
    uint32_t* sWp = smw + EW_SW;
    float* sV = (float*)(smw + EW_SV);
    float* sU = (float*)(smw + EW_SU);
    const uint32_t sb = smem_u32(smw);

    const int tid = threadIdx.x;

    // ---- stage W_edge once; hoist B fragments ----
    {
        const float* wedge = wl + 256 * 128;
        for (int i = tid; i < 8192; i += 512) {
            const int kp = i >> 7, n = i & 127;
            sWp[kp * 136 + n] = packbf(wedge[(2 * kp) * 128 + n],
                                       wedge[(2 * kp + 1) * 128 + n]);
        }
    }
    __syncthreads();

    const int w    = tid >> 5;
    const int lane = tid & 31;
    const int wm   = w & 3;
    const int wn   = w >> 2;
    const int g    = lane >> 2;
    const int tig  = lane & 3;

    uint32_t bB[8][4][2];
    #pragma unroll
    for (int ks = 0; ks < 8; ks++)
        #pragma unroll
        for (int nt = 0; nt < 4; nt++) {
            const int n = wn * 32 + nt * 8 + g;
            bB[ks][nt][0] = sWp[(ks * 8 + tig) * 136 + n];
            bB[ks][nt][1] = sWp[(ks * 8 + tig + 4) * 136 + n];
        }

    const int quad  = lane >> 3;
    const int r8    = lane & 7;
    const int rowL  = wm * 16 + (quad & 1) * 8 + r8;
    const int koffL = (quad >> 1) * 4;
    const uint32_t aAddr0 = sb + (EW_SA + rowL * 68 + koffL) * 4u;

    const int nsrc_a[4] = {64, 128, 128, 128};
    const int ndst_a[4] = {128, 128, 128, 10};
    const int eb_a  [4] = {0, 8192, 24576, 40960};
    const int so_a  [4] = {0, 64, 192, 320};
    const int do_a  [4] = {64, 192, 320, 448};

    // ---- persistent item loop ----
    for (int item = blockIdx.x; item < N_ITEMS; item += EDGE_GRID) {
        const int b = item / 42;
        const int r = item % 42;
        int lb, dtile, chunk, s_begin;
        if (r < 8)       { lb = 0; dtile = r >> 2;          chunk = r & 3;
                           s_begin = chunk * 16; }
        else if (r < 24) { lb = 1; const int q = r - 8;  dtile = q & 1; chunk = q >> 1;
                           s_begin = chunk * 16; }
        else if (r < 40) { lb = 2; const int q = r - 24; dtile = q & 1; chunk = q >> 1;
                           s_begin = chunk * 16; }
        else             { lb = 3; const int q = r - 40; dtile = 0;     chunk = q * 4;
                           s_begin = q * 64; }

        const int n_src = nsrc_a[lb];
        const int n_dst = ndst_a[lb];
        const int ebase = eb_a[lb];
        const int soff  = so_a[lb];
        const int doff  = do_a[lb];
        const int d0    = dtile * 64;

        const bool packed4 = (lb == 3);
        const int sshift = packed4 ? 4 : 6;
        const int rmask  = packed4 ? 15 : 63;
        const int sstep  = packed4 ? 4 : 1;
        const int nsrow  = packed4 ? 4 : 1;

        auto stageA = [&](int buf, int i) {
            const uint32_t dbase = sb + (EW_SA + buf * 4352) * 4;
            const int s0 = s_begin + i * sstep;
            #pragma unroll
            for (int j = 0; j < 2; j++) {
                const int idx = tid + 512 * j;
                const int row = idx >> 4, c = idx & 15;
                const int dgl = row & rmask;
                const int s   = s0 + (row >> sshift);
                const bool ok = (d0 + dgl < n_dst);
                const size_t e = (size_t)b * EE + ebase +
                                 (ok ? ((size_t)s * n_dst + d0 + dgl) : 0);
                cp16(dbase + (uint32_t)(row * 68 + c * 4) * 4u,
                     g_ebf + e * 16 + c, ok ? 16u : 0u);
            }
        };
        auto stageU = [&](int slot, int i) {
            if (tid < 32 * nsrow) {
                const int sl = tid >> 5, c4 = tid & 31;
                cp16(sb + (EW_SU + slot * 512 + sl * 128 + c4 * 4) * 4u,
                     g_u + ((size_t)b * NN + soff + s_begin + i * sstep + sl) * DD + c4 * 4,
                     16u);
            }
        };

        // stage V tile (+ prologue tiles 0,1)
        stageA(0, 0); stageU(0, 0);
        asm volatile("cp.async.commit_group;" ::: "memory");
        stageA(1, 1); stageU(1, 1);
        asm volatile("cp.async.commit_group;" ::: "memory");

        for (int i = tid; i < 2048; i += 512) {
            const int row = i >> 5, c4 = i & 31;
            const int dgl = row & rmask;
            float4 v4 = make_float4(0.f, 0.f, 0.f, 0.f);
            if (d0 + dgl < n_dst)
                v4 = *(const float4*)(g_v + ((size_t)b * NN + doff + d0 + dgl) * DD + c4 * 4);
            *(float4*)(sV + row * 132 + c4 * 4) = v4;
        }
        asm volatile("cp.async.wait_group 1;" ::: "memory");
        __syncthreads();

        float agg[4][4];
        #pragma unroll
        for (int nt = 0; nt < 4; nt++)
            #pragma unroll
            for (int rr = 0; rr < 4; rr++) agg[nt][rr] = 0.f;

        // ---- 16 uniform iterations ----
        for (int i = 0; i < 16; i++) {
            const int p = i % 3;
            if (i + 2 < 16) {
                stageA((i + 2) % 3, i + 2);
                stageU((i + 2) % 3, i + 2);
            }
            asm volatile("cp.async.commit_group;" ::: "memory");

            float acc[4][4];
            #pragma unroll
            for (int nt = 0; nt < 4; nt++)
                #pragma unroll
                for (int rr = 0; rr < 4; rr++) acc[nt][rr] = 0.f;

            const uint32_t aBase = aAddr0 + (uint32_t)p * (4352u * 4u);
            #pragma unroll
            for (int ks = 0; ks < 8; ks++) {
                uint32_t a0, a1, a2, a3;
                ldsm_x4(a0, a1, a2, a3, aBase + (uint32_t)ks * 32u);
                #pragma unroll
                for (int nt = 0; nt < 4; nt++)
                    mma16(acc[nt][0], acc[nt][1], acc[nt][2], acc[nt][3],
                          a0, a1, a2, a3, bB[ks][nt][0], bB[ks][nt][1]);
            }

            const float* sUp = sU + p * 512 + (packed4 ? wm * 128 : 0);
            const int r0 = wm * 16 + g;
            #pragma unroll
            for (int nt = 0; nt < 4; nt++) {
                const int col = wn * 32 + nt * 8 + 2 * tig;
                const float2 uu = *(const float2*)(sUp + col);
                const float2 v0 = *(const float2*)(sV + r0 * 132 + col);
                const float2 v1 = *(const float2*)(sV + (r0 + 8) * 132 + col);
                agg[nt][0] += fmaxf(acc[nt][0] + uu.x + v0.x, 0.f);
                agg[nt][1] += fmaxf(acc[nt][1] + uu.y + v0.y, 0.f);
                agg[nt][2] += fmaxf(acc[nt][2] + uu.x + v1.x, 0.f);
                agg[nt][3] += fmaxf(acc[nt][3] + uu.y + v1.y, 0.f);
            }

            asm volatile("cp.async.wait_group 1;" ::: "memory");
            __syncthreads();
        }

        // ---- store partial agg (scaled) ----
        const float scale = 1.f / (float)n_src;
        const int chunkbuf = packed4 ? (chunk + wm) : chunk;
        float* aggbuf = g_agg + (size_t)chunkbuf * AGG_STRIDE;
        const int dg0 = d0 + ((wm * 16 + g) & rmask);
        const int dg1 = d0 + ((wm * 16 + g + 8) & rmask);
        #pragma unroll
        for (int nt = 0; nt < 4; nt++) {
            const int col = wn * 32 + nt * 8 + 2 * tig;
            if (dg0 < n_dst)
                *(float2*)(aggbuf + ((size_t)b * NN + doff + dg0) * DD + col) =
                    make_float2(agg[nt][0] * scale, agg[nt][1] * scale);
            if (dg1 < n_dst)
                *(float2*)(aggbuf + ((size_t)b * NN + doff + dg1) * DD + col) =
                    make_float2(agg[nt][2] * scale, agg[nt][3] * scale);
        }
        __syncthreads();   // agg stores independent; protect sV/sU reuse next item
    }
}

// ---------------------------------------------------------------------------
// self_uv_tf32: 32-row tiles, 229 CTAs, 256 threads, tf32 mma.
//  1) x_new = relu(x@Wself + b + sum_{nbuf} agg) -> g_x + xn (tf32)
//  2) u = xn@Wsrc -> g_u ;  3) v = xn@Wdst + b_msg -> g_v
// ---------------------------------------------------------------------------
#define SU_XS 0
#define SU_XN 4224                   // 32*132
#define SU_W  8448
#define SU_WORDS (SU_W + 128 * 136)
#define SU_SMEM_BYTES (SU_WORDS * 4)

__global__ __launch_bounds__(256, 2) void self_uv_tf32(const float* __restrict__ xin,
                                                       const float* __restrict__ wself,
                                                       const float* __restrict__ bself,
                                                       const float* __restrict__ wnext,
                                                       const float* __restrict__ bnext)
{
    extern __shared__ float smf[];
    float* xs = smf + SU_XS;
    float* xn = smf + SU_XN;
    float* sW = smf + SU_W;

    const int tid  = threadIdx.x;
    const int row0 = blockIdx.x * 32;
    const float* x = (xin != nullptr) ? xin : g_x;

    auto stageW = [&](const float* wsrc) {
        for (int i = tid; i < 4096; i += 256) {
            const int kr = i >> 5, c4 = i & 31;
            float4 wv = *(const float4*)(wsrc + kr * 128 + c4 * 4);
            wv.x = to_tf32(wv.x); wv.y = to_tf32(wv.y);
            wv.z = to_tf32(wv.z); wv.w = to_tf32(wv.w);
            *(float4*)(sW + kr * 136 + c4 * 4) = wv;
        }
    };

    {
        float* xt = (wself != nullptr) ? xs : xn;
        for (int i = tid; i < 1024; i += 256) {
            const int r = i >> 5, c4 = i & 31;
            float4 xv = *(const float4*)(x + (size_t)(row0 + r) * DD + c4 * 4);
            xv.x = to_tf32(xv.x); xv.y = to_tf32(xv.y);
            xv.z = to_tf32(xv.z); xv.w = to_tf32(xv.w);
            *(float4*)(xt + r * 132 + c4 * 4) = xv;
        }
    }
    if (wself != nullptr) stageW(wself);
    __syncthreads();

    // warp tiling: wm = w&1 (16 rows), wn = w>>1 (32 cols, 4 n-frags)
    const int w    = tid >> 5;
    const int lane = tid & 31;
    const int wm   = w & 1;
    const int wn   = w >> 1;
    const int g    = lane >> 2;
    const int tig  = lane & 3;
    const int rowg0 = row0 + wm * 16 + g;

    const uint32_t* sWu = (const uint32_t*)sW;

    auto gemm = [&](const float* A, float (&acc)[4][4]) {
        #pragma unroll
        for (int nt = 0; nt < 4; nt++)
            #pragma unroll
            for (int rr = 0; rr < 4; rr++) acc[nt][rr] = 0.f;
        const uint32_t* Au = (const uint32_t*)A;
        const int base0 = (wm * 16 + g) * 132;
        #pragma unroll
        for (int ks = 0; ks < 16; ks++) {
            const int kb = ks * 8;
            const uint32_t a0 = Au[base0 + kb + tig];
            const uint32_t a1 = Au[base0 + 8 * 132 + kb + tig];
            const uint32_t a2 = Au[base0 + kb + tig + 4];
            const uint32_t a3 = Au[base0 + 8 * 132 + kb + tig + 4];
            #pragma unroll
            for (int nt = 0; nt < 4; nt++) {
                const int n = wn * 32 + nt * 8 + g;
                const uint32_t b0 = sWu[(kb + tig) * 136 + n];
                const uint32_t b1 = sWu[(kb + tig + 4) * 136 + n];
                mma8(acc[nt][0], acc[nt][1], acc[nt][2], acc[nt][3],
                     a0, a1, a2, a3, b0, b1);
            }
        }
    };

    if (wself != nullptr) {
        float acc[4][4];
        gemm(xs, acc);

        #pragma unroll
        for (int rr = 0; rr < 2; rr++) {
            const int row = rowg0 + rr * 8;
            const int nodeidx = row % NN;
            const bool hasagg = (nodeidx >= 64);
            const int nbuf = (nodeidx < 192) ? 4 : 8;
            #pragma unroll
            for (int nt = 0; nt < 4; nt++) {
                const int col = wn * 32 + nt * 8 + 2 * tig;
                float c0 = acc[nt][rr * 2 + 0] + __ldg(bself + col);
                float c1 = acc[nt][rr * 2 + 1] + __ldg(bself + col + 1);
                if (hasagg) {
                    const size_t o = (size_t)row * DD + col;
                    for (int cb = 0; cb < nbuf; cb++) {
                        const float2 av = *(const float2*)(g_agg + (size_t)cb * AGG_STRIDE + o);
                        c0 += av.x; c1 += av.y;
                    }
                }
                c0 = fmaxf(c0, 0.f);
                c1 = fmaxf(c1, 0.f);
                *(float2*)(g_x + (size_t)row * DD + col) = make_float2(c0, c1);
                *(float2*)(xn + (wm * 16 + g + rr * 8) * 132 + col) =
                    make_float2(to_tf32(c0), to_tf32(c1));
            }
        }
        __syncthreads();
    }

    if (wnext != nullptr) {
        #pragma unroll
        for (int pass = 0; pass < 2; pass++) {
            stageW(wnext + (size_t)pass * 128 * 128);
            __syncthreads();

            float acc[4][4];
            gemm(xn, acc);

            float* gout = (pass == 0) ? g_u : g_v;
            #pragma unroll
            for (int rr = 0; rr < 2; rr++) {
                const int row = rowg0 + rr * 8;
                #pragma unroll
                for (int nt = 0; nt < 4; nt++) {
                    const int col = wn * 32 + nt * 8 + 2 * tig;
                    float c0 = acc[nt][rr * 2 + 0];
                    float c1 = acc[nt][rr * 2 + 1];
                    if (pass == 1) {
                        c0 += __ldg(bnext + col);
                        c1 += __ldg(bnext + col + 1);
                    }
                    *(float2*)(gout + (size_t)row * DD + col) = make_float2(c0, c1);
                }
            }
            if (pass == 0) __syncthreads();
        }
    }
}

// ---------------------------------------------------------------------------
// head kernel
// ---------------------------------------------------------------------------
__global__ __launch_bounds__(128) void head_kernel(const float* __restrict__ w1,
                                                   const float* __restrict__ b1,
                                                   const float* __restrict__ w2,
                                                   const float* __restrict__ b2,
                                                   const float* __restrict__ w3,
                                                   const float* __restrict__ b3,
                                                   float* __restrict__ out)
{
    __shared__ float g[128];
    __shared__ float h[128];
    const int b = blockIdx.x;
    const int t = threadIdx.x;

    float s = 0.f;
    const float* xb = g_x + (size_t)b * NN * DD;
    for (int n = 0; n < NN; n++) s += xb[(size_t)n * DD + t];
    g[t] = s * (1.f / (float)NN);
    __syncthreads();

    float acc = 0.f;
    #pragma unroll 4
    for (int k = 0; k < 128; k++) acc += g[k] * __ldg(w1 + k * 128 + t);
    h[t] = fmaxf(acc + b1[t], 0.f);
    __syncthreads();

    acc = 0.f;
    #pragma unroll 4
    for (int k = 0; k < 128; k++) acc += h[k] * __ldg(w2 + k * 128 + t);
    __syncthreads();
    g[t] = fmaxf(acc + b2[t], 0.f);
    __syncthreads();

    if (t < 10) {
        float o = b3[t];
        for (int k = 0; k < 128; k++) o += g[k] * __ldg(w3 + k * 10 + t);
        out[b * 10 + t] = o;
    }
}

// ---------------------------------------------------------------------------
// launch
// ---------------------------------------------------------------------------
extern "C" void kernel_launch(void* const* d_in, const int* in_sizes, int n_in,
                              void* d_out, int out_size)
{
    (void)in_sizes; (void)n_in; (void)out_size;
    const float* node_features = (const float*)d_in[0];
    const float* edge_attr     = (const float*)d_in[1];
    const float* w_msg         = (const float*)d_in[2];
    const float* b_msg         = (const float*)d_in[3];
    const float* w_self        = (const float*)d_in[4];
    const float* b_self        = (const float*)d_in[5];
    const float* w1            = (const float*)d_in[6];
    const float* b1            = (const float*)d_in[7];
    const float* w2            = (const float*)d_in[8];
    const float* b2            = (const float*)d_in[9];
    const float* w3            = (const float*)d_in[10];
    const float* b3            = (const float*)d_in[11];
    float* out = (float*)d_out;

    cudaFuncSetAttribute(edge_kernel, cudaFuncAttributeMaxDynamicSharedMemorySize,
                         EDGE_SMEM_BYTES);
    cudaFuncSetAttribute(self_uv_tf32, cudaFuncAttributeMaxDynamicSharedMemorySize,
                         SU_SMEM_BYTES);

    prepack_kernel<<<42240, 256>>>(edge_attr);

    // layer-0 u,v (uv-only mode)
    self_uv_tf32<<<229, 256, SU_SMEM_BYTES>>>(node_features, nullptr, nullptr,
                                              w_msg, b_msg);

    for (int l = 0; l < 3; l++) {
        const float* wl = w_msg + (size_t)l * 384 * 128;
        edge_kernel<<<EDGE_GRID, 512, EDGE_SMEM_BYTES>>>(wl);

        const float* xin = (l == 0) ? node_features : nullptr;
        const float* wn  = (l < 2) ? w_msg + (size_t)(l + 1) * 384 * 128 : nullptr;
        const float* bn  = (l < 2) ? b_msg + (size_t)(l + 1) * 128 : nullptr;
        self_uv_tf32<<<229, 256, SU_SMEM_BYTES>>>(xin, w_self + (size_t)l * 128 * 128,
                                                  b_self + (size_t)l * 128, wn, bn);
    }
    head_kernel<<<16, 128>>>(w1, b1, w2, b2, w3, b3, out);
}

// round 11
// speedup vs baseline: 9.6752x; 1.0020x over previous
#include <cuda_runtime.h>
#include <cuda_bf16.h>
#include <cstdint>
#include <cstddef>

#define BB 16
#define NN 458
#define DD 128
#define EE 42240
#define NROWS (BB * NN)              // 7328
#define AGG_STRIDE (BB * NN * DD)
#define N_ITEMS 672                  // 42 items/batch * 16 batches
#define EDGE_GRID 148

// ---------------------------------------------------------------------------
// Scratch (device globals; no allocation allowed)
// ---------------------------------------------------------------------------
__device__ float g_x  [BB * NN * DD];        // current node features
__device__ float g_u  [BB * NN * DD];        // x @ W_src
__device__ float g_v  [BB * NN * DD];        // x @ W_dst + b_msg
__device__ float g_agg[8 * BB * NN * DD];    // eight partial agg buffers
__device__ uint4 g_ebf[BB * EE * 16];        // edge_attr prepacked bf16x2

// ---------------------------------------------------------------------------
// helpers
// ---------------------------------------------------------------------------
__device__ __forceinline__ uint32_t packbf(float lo, float hi) {
    uint32_t r;
    asm("cvt.rn.bf16x2.f32 %0, %1, %2;" : "=r"(r) : "f"(hi), "f"(lo));
    return r;
}

__device__ __forceinline__ float to_tf32(float x) {
    uint32_t u;
    asm("cvt.rna.tf32.f32 %0, %1;" : "=r"(u) : "f"(x));
    return __uint_as_float(u);
}

__device__ __forceinline__ uint32_t smem_u32(const void* p) {
    uint32_t a;
    asm("{ .reg .u64 t; cvta.to.shared.u64 t, %1; cvt.u32.u64 %0, t; }"
        : "=r"(a) : "l"(p));
    return a;
}

__device__ __forceinline__ void mma16(float& c0, float& c1, float& c2, float& c3,
                                      uint32_t a0, uint32_t a1, uint32_t a2, uint32_t a3,
                                      uint32_t b0, uint32_t b1) {
    asm volatile(
        "mma.sync.aligned.m16n8k16.row.col.f32.bf16.bf16.f32 "
        "{%0,%1,%2,%3},{%4,%5,%6,%7},{%8,%9},{%0,%1,%2,%3};"
        : "+f"(c0), "+f"(c1), "+f"(c2), "+f"(c3)
        : "r"(a0), "r"(a1), "r"(a2), "r"(a3), "r"(b0), "r"(b1));
}

__device__ __forceinline__ void mma8(float& c0, float& c1, float& c2, float& c3,
                                     uint32_t a0, uint32_t a1, uint32_t a2, uint32_t a3,
                                     uint32_t b0, uint32_t b1) {
    asm volatile(
        "mma.sync.aligned.m16n8k8.row.col.f32.tf32.tf32.f32 "
        "{%0,%1,%2,%3},{%4,%5,%6,%7},{%8,%9},{%0,%1,%2,%3};"
        : "+f"(c0), "+f"(c1), "+f"(c2), "+f"(c3)
        : "r"(a0), "r"(a1), "r"(a2), "r"(a3), "r"(b0), "r"(b1));
}

__device__ __forceinline__ void ldsm_x4(uint32_t& r0, uint32_t& r1, uint32_t& r2,
                                        uint32_t& r3, uint32_t addr) {
    asm volatile("ldmatrix.sync.aligned.m8n8.x4.shared.b16 {%0,%1,%2,%3}, [%4];"
                 : "=r"(r0), "=r"(r1), "=r"(r2), "=r"(r3) : "r"(addr));
}

__device__ __forceinline__ void cp16(uint32_t daddr, const void* gptr, uint32_t srcsize) {
    asm volatile("cp.async.cg.shared.global [%0], [%1], 16, %2;"
                 :: "r"(daddr), "l"(gptr), "r"(srcsize) : "memory");
}

// ---------------------------------------------------------------------------
// prepack kernel: edge_attr fp32 -> bf16x2 packed
// ---------------------------------------------------------------------------
__global__ __launch_bounds__(256) void prepack_kernel(const float* __restrict__ ea)
{
    const size_t i = (size_t)blockIdx.x * 256 + threadIdx.x;
    const float4 f0 = *(const float4*)(ea + i * 8);
    const float4 f1 = *(const float4*)(ea + i * 8 + 4);
    g_ebf[i] = make_uint4(packbf(f0.x, f0.y), packbf(f0.z, f0.w),
                          packbf(f1.x, f1.y), packbf(f1.z, f1.w));
}

// ---------------------------------------------------------------------------
// persistent edge kernel: 148 CTAs, 512 threads, 672 uniform items (16 iters).
// item = (batch, block, 64-dst tile, 16-src chunk)  [block 3: 4-src packed]
// W_edge staged + B-fragments hoisted ONCE per CTA; triple-buffered cp.async.
// ---------------------------------------------------------------------------
#define EW_SW 0
#define EW_SA 8704                     // 3 x 4352 A buffers
#define EW_SV (EW_SA + 3 * 4352)       // V tile 64x132
#define EW_SU (EW_SV + 64 * 132)       // 3 slots x 512 floats
#define EDGE_SMEM_WORDS (EW_SU + 3 * 512)
#define EDGE_SMEM_BYTES (EDGE_SMEM_WORDS * 4)

__global__ __launch_bounds__(512, 1) void edge_kernel(const float* __restrict__ wl)
{
    extern __shared__ uint32_t smw[];
    uint32_t* sWp = smw + EW_SW;
    float* sV = (float*)(smw + EW_SV);
    float* sU = (float*)(smw + EW_SU);
    const uint32_t sb = smem_u32(smw);

    const int tid = threadIdx.x;

    // ---- stage W_edge once; hoist B fragments ----
    {
        const float* wedge = wl + 256 * 128;
        for (int i = tid; i < 8192; i += 512) {
            const int kp = i >> 7, n = i & 127;
            sWp[kp * 136 + n] = packbf(wedge[(2 * kp) * 128 + n],
                                       wedge[(2 * kp + 1) * 128 + n]);
        }
    }
    __syncthreads();

    const int w    = tid >> 5;
    const int lane = tid & 31;
    const int wm   = w & 3;
    const int wn   = w >> 2;
    const int g    = lane >> 2;
    const int tig  = lane & 3;

    uint32_t bB[8][4][2];
    #pragma unroll
    for (int ks = 0; ks < 8; ks++)
        #pragma unroll
        for (int nt = 0; nt < 4; nt++) {
            const int n = wn * 32 + nt * 8 + g;
            bB[ks][nt][0] = sWp[(ks * 8 + tig) * 136 + n];
            bB[ks][nt][1] = sWp[(ks * 8 + tig + 4) * 136 + n];
        }

    const int quad  = lane >> 3;
    const int r8    = lane & 7;
    const int rowL  = wm * 16 + (quad & 1) * 8 + r8;
    const int koffL = (quad >> 1) * 4;
    const uint32_t aAddr0 = sb + (EW_SA + rowL * 68 + koffL) * 4u;

    const int nsrc_a[4] = {64, 128, 128, 128};
    const int ndst_a[4] = {128, 128, 128, 10};
    const int eb_a  [4] = {0, 8192, 24576, 40960};
    const int so_a  [4] = {0, 64, 192, 320};
    const int do_a  [4] = {64, 192, 320, 448};

    // ---- persistent item loop ----
    for (int item = blockIdx.x; item < N_ITEMS; item += EDGE_GRID) {
        const int b = item / 42;
        const int r = item % 42;
        int lb, dtile, chunk, s_begin;
        if (r < 8)       { lb = 0; dtile = r >> 2;          chunk = r & 3;
                           s_begin = chunk * 16; }
        else if (r < 24) { lb = 1; const int q = r - 8;  dtile = q & 1; chunk = q >> 1;
                           s_begin = chunk * 16; }
        else if (r < 40) { lb = 2; const int q = r - 24; dtile = q & 1; chunk = q >> 1;
                           s_begin = chunk * 16; }
        else             { lb = 3; const int q = r - 40; dtile = 0;     chunk = q * 4;
                           s_begin = q * 64; }

        const int n_src = nsrc_a[lb];
        const int n_dst = ndst_a[lb];
        const int ebase = eb_a[lb];
        const int soff  = so_a[lb];
        const int doff  = do_a[lb];
        const int d0    = dtile * 64;

        const bool packed4 = (lb == 3);
        const int sshift = packed4 ? 4 : 6;
        const int rmask  = packed4 ? 15 : 63;
        const int sstep  = packed4 ? 4 : 1;
        const int nsrow  = packed4 ? 4 : 1;

        auto stageA = [&](int buf, int i) {
            const uint32_t dbase = sb + (EW_SA + buf * 4352) * 4;
            const int s0 = s_begin + i * sstep;
            #pragma unroll
            for (int j = 0; j < 2; j++) {
                const int idx = tid + 512 * j;
                const int row = idx >> 4, c = idx & 15;
                const int dgl = row & rmask;
                const int s   = s0 + (row >> sshift);
                const bool ok = (d0 + dgl < n_dst);
                const size_t e = (size_t)b * EE + ebase +
                                 (ok ? ((size_t)s * n_dst + d0 + dgl) : 0);
                cp16(dbase + (uint32_t)(row * 68 + c * 4) * 4u,
                     g_ebf + e * 16 + c, ok ? 16u : 0u);
            }
        };
        auto stageU = [&](int slot, int i) {
            if (tid < 32 * nsrow) {
                const int sl = tid >> 5, c4 = tid & 31;
                cp16(sb + (EW_SU + slot * 512 + sl * 128 + c4 * 4) * 4u,
                     g_u + ((size_t)b * NN + soff + s_begin + i * sstep + sl) * DD + c4 * 4,
                     16u);
            }
        };

        // stage V tile (+ prologue tiles 0,1)
        stageA(0, 0); stageU(0, 0);
        asm volatile("cp.async.commit_group;" ::: "memory");
        stageA(1, 1); stageU(1, 1);
        asm volatile("cp.async.commit_group;" ::: "memory");

        for (int i = tid; i < 2048; i += 512) {
            const int row = i >> 5, c4 = i & 31;
            const int dgl = row & rmask;
            float4 v4 = make_float4(0.f, 0.f, 0.f, 0.f);
            if (d0 + dgl < n_dst)
                v4 = *(const float4*)(g_v + ((size_t)b * NN + doff + d0 + dgl) * DD + c4 * 4);
            *(float4*)(sV + row * 132 + c4 * 4) = v4;
        }
        asm volatile("cp.async.wait_group 1;" ::: "memory");
        __syncthreads();

        float agg[4][4];
        #pragma unroll
        for (int nt = 0; nt < 4; nt++)
            #pragma unroll
            for (int rr = 0; rr < 4; rr++) agg[nt][rr] = 0.f;

        // ---- 16 uniform iterations ----
        for (int i = 0; i < 16; i++) {
            const int p = i % 3;
            if (i + 2 < 16) {
                stageA((i + 2) % 3, i + 2);
                stageU((i + 2) % 3, i + 2);
            }
            asm volatile("cp.async.commit_group;" ::: "memory");

            float acc[4][4];
            #pragma unroll
            for (int nt = 0; nt < 4; nt++)
                #pragma unroll
                for (int rr = 0; rr < 4; rr++) acc[nt][rr] = 0.f;

            const uint32_t aBase = aAddr0 + (uint32_t)p * (4352u * 4u);
            #pragma unroll
            for (int ks = 0; ks < 8; ks++) {
                uint32_t a0, a1, a2, a3;
                ldsm_x4(a0, a1, a2, a3, aBase + (uint32_t)ks * 32u);
                #pragma unroll
                for (int nt = 0; nt < 4; nt++)
                    mma16(acc[nt][0], acc[nt][1], acc[nt][2], acc[nt][3],
                          a0, a1, a2, a3, bB[ks][nt][0], bB[ks][nt][1]);
            }

            const float* sUp = sU + p * 512 + (packed4 ? wm * 128 : 0);
            const int r0 = wm * 16 + g;
            #pragma unroll
            for (int nt = 0; nt < 4; nt++) {
                const int col = wn * 32 + nt * 8 + 2 * tig;
                const float2 uu = *(const float2*)(sUp + col);
                const float2 v0 = *(const float2*)(sV + r0 * 132 + col);
                const float2 v1 = *(const float2*)(sV + (r0 + 8) * 132 + col);
                agg[nt][0] += fmaxf(acc[nt][0] + uu.x + v0.x, 0.f);
                agg[nt][1] += fmaxf(acc[nt][1] + uu.y + v0.y, 0.f);
                agg[nt][2] += fmaxf(acc[nt][2] + uu.x + v1.x, 0.f);
                agg[nt][3] += fmaxf(acc[nt][3] + uu.y + v1.y, 0.f);
            }

            asm volatile("cp.async.wait_group 1;" ::: "memory");
            __syncthreads();
        }

        // ---- store partial agg (scaled) ----
        const float scale = 1.f / (float)n_src;
        const int chunkbuf = packed4 ? (chunk + wm) : chunk;
        float* aggbuf = g_agg + (size_t)chunkbuf * AGG_STRIDE;
        const int dg0 = d0 + ((wm * 16 + g) & rmask);
        const int dg1 = d0 + ((wm * 16 + g + 8) & rmask);
        #pragma unroll
        for (int nt = 0; nt < 4; nt++) {
            const int col = wn * 32 + nt * 8 + 2 * tig;
            if (dg0 < n_dst)
                *(float2*)(aggbuf + ((size_t)b * NN + doff + dg0) * DD + col) =
                    make_float2(agg[nt][0] * scale, agg[nt][1] * scale);
            if (dg1 < n_dst)
                *(float2*)(aggbuf + ((size_t)b * NN + doff + dg1) * DD + col) =
                    make_float2(agg[nt][2] * scale, agg[nt][3] * scale);
        }
        __syncthreads();   // agg stores independent; protect sV/sU reuse next item
    }
}

// ---------------------------------------------------------------------------
// self_uv_tf32: 32-row tiles, 229 CTAs, 256 threads, tf32 mma.
//  1) x_new = relu(x@Wself + b + sum_{nbuf} agg) -> g_x + xn (tf32)
//  2) u = xn@Wsrc -> g_u ;  3) v = xn@Wdst + b_msg -> g_v
// ---------------------------------------------------------------------------
#define SU_XS 0
#define SU_XN 4224                   // 32*132
#define SU_W  8448
#define SU_WORDS (SU_W + 128 * 136)
#define SU_SMEM_BYTES (SU_WORDS * 4)

__global__ __launch_bounds__(256, 2) void self_uv_tf32(const float* __restrict__ xin,
                                                       const float* __restrict__ wself,
                                                       const float* __restrict__ bself,
                                                       const float* __restrict__ wnext,
                                                       const float* __restrict__ bnext)
{
    extern __shared__ float smf[];
    float* xs = smf + SU_XS;
    float* xn = smf + SU_XN;
    float* sW = smf + SU_W;

    const int tid  = threadIdx.x;
    const int row0 = blockIdx.x * 32;
    const float* x = (xin != nullptr) ? xin : g_x;

    auto stageW = [&](const float* wsrc) {
        for (int i = tid; i < 4096; i += 256) {
            const int kr = i >> 5, c4 = i & 31;
            float4 wv = *(const float4*)(wsrc + kr * 128 + c4 * 4);
            wv.x = to_tf32(wv.x); wv.y = to_tf32(wv.y);
            wv.z = to_tf32(wv.z); wv.w = to_tf32(wv.w);
            *(float4*)(sW + kr * 136 + c4 * 4) = wv;
        }
    };

    {
        float* xt = (wself != nullptr) ? xs : xn;
        for (int i = tid; i < 1024; i += 256) {
            const int r = i >> 5, c4 = i & 31;
            float4 xv = *(const float4*)(x + (size_t)(row0 + r) * DD + c4 * 4);
            xv.x = to_tf32(xv.x); xv.y = to_tf32(xv.y);
            xv.z = to_tf32(xv.z); xv.w = to_tf32(xv.w);
            *(float4*)(xt + r * 132 + c4 * 4) = xv;
        }
    }
    if (wself != nullptr) stageW(wself);
    __syncthreads();

    // warp tiling: wm = w&1 (16 rows), wn = w>>1 (32 cols, 4 n-frags)
    const int w    = tid >> 5;
    const int lane = tid & 31;
    const int wm   = w & 1;
    const int wn   = w >> 1;
    const int g    = lane >> 2;
    const int tig  = lane & 3;
    const int rowg0 = row0 + wm * 16 + g;

    const uint32_t* sWu = (const uint32_t*)sW;

    auto gemm = [&](const float* A, float (&acc)[4][4]) {
        #pragma unroll
        for (int nt = 0; nt < 4; nt++)
            #pragma unroll
            for (int rr = 0; rr < 4; rr++) acc[nt][rr] = 0.f;
        const uint32_t* Au = (const uint32_t*)A;
        const int base0 = (wm * 16 + g) * 132;
        #pragma unroll
        for (int ks = 0; ks < 16; ks++) {
            const int kb = ks * 8;
            const uint32_t a0 = Au[base0 + kb + tig];
            const uint32_t a1 = Au[base0 + 8 * 132 + kb + tig];
            const uint32_t a2 = Au[base0 + kb + tig + 4];
            const uint32_t a3 = Au[base0 + 8 * 132 + kb + tig + 4];
            #pragma unroll
            for (int nt = 0; nt < 4; nt++) {
                const int n = wn * 32 + nt * 8 + g;
                const uint32_t b0 = sWu[(kb + tig) * 136 + n];
                const uint32_t b1 = sWu[(kb + tig + 4) * 136 + n];
                mma8(acc[nt][0], acc[nt][1], acc[nt][2], acc[nt][3],
                     a0, a1, a2, a3, b0, b1);
            }
        }
    };

    if (wself != nullptr) {
        float acc[4][4];
        gemm(xs, acc);

        #pragma unroll
        for (int rr = 0; rr < 2; rr++) {
            const int row = rowg0 + rr * 8;
            const int nodeidx = row % NN;
            const bool hasagg = (nodeidx >= 64);
            const int nbuf = (nodeidx < 192) ? 4 : 8;
            #pragma unroll
            for (int nt = 0; nt < 4; nt++) {
                const int col = wn * 32 + nt * 8 + 2 * tig;
                float c0 = acc[nt][rr * 2 + 0] + __ldg(bself + col);
                float c1 = acc[nt][rr * 2 + 1] + __ldg(bself + col + 1);
                if (hasagg) {
                    const size_t o = (size_t)row * DD + col;
                    for (int cb = 0; cb < nbuf; cb++) {
                        const float2 av = *(const float2*)(g_agg + (size_t)cb * AGG_STRIDE + o);
                        c0 += av.x; c1 += av.y;
                    }
                }
                c0 = fmaxf(c0, 0.f);
                c1 = fmaxf(c1, 0.f);
                *(float2*)(g_x + (size_t)row * DD + col) = make_float2(c0, c1);
                *(float2*)(xn + (wm * 16 + g + rr * 8) * 132 + col) =
                    make_float2(to_tf32(c0), to_tf32(c1));
            }
        }
        __syncthreads();
    }

    if (wnext != nullptr) {
        #pragma unroll
        for (int pass = 0; pass < 2; pass++) {
            stageW(wnext + (size_t)pass * 128 * 128);
            __syncthreads();

            float acc[4][4];
            gemm(xn, acc);

            float* gout = (pass == 0) ? g_u : g_v;
            #pragma unroll
            for (int rr = 0; rr < 2; rr++) {
                const int row = rowg0 + rr * 8;
                #pragma unroll
                for (int nt = 0; nt < 4; nt++) {
                    const int col = wn * 32 + nt * 8 + 2 * tig;
                    float c0 = acc[nt][rr * 2 + 0];
                    float c1 = acc[nt][rr * 2 + 1];
                    if (pass == 1) {
                        c0 += __ldg(bnext + col);
                        c1 += __ldg(bnext + col + 1);
                    }
                    *(float2*)(gout + (size_t)row * DD + col) = make_float2(c0, c1);
                }
            }
            if (pass == 0) __syncthreads();
        }
    }
}

// ---------------------------------------------------------------------------
// head kernel
// ---------------------------------------------------------------------------
__global__ __launch_bounds__(128) void head_kernel(const float* __restrict__ w1,
                                                   const float* __restrict__ b1,
                                                   const float* __restrict__ w2,
                                                   const float* __restrict__ b2,
                                                   const float* __restrict__ w3,
                                                   const float* __restrict__ b3,
                                                   float* __restrict__ out)
{
    __shared__ float g[128];
    __shared__ float h[128];
    const int b = blockIdx.x;
    const int t = threadIdx.x;

    float s = 0.f;
    const float* xb = g_x + (size_t)b * NN * DD;
    for (int n = 0; n < NN; n++) s += xb[(size_t)n * DD + t];
    g[t] = s * (1.f / (float)NN);
    __syncthreads();

    float acc = 0.f;
    #pragma unroll 4
    for (int k = 0; k < 128; k++) acc += g[k] * __ldg(w1 + k * 128 + t);
    h[t] = fmaxf(acc + b1[t], 0.f);
    __syncthreads();

    acc = 0.f;
    #pragma unroll 4
    for (int k = 0; k < 128; k++) acc += h[k] * __ldg(w2 + k * 128 + t);
    __syncthreads();
    g[t] = fmaxf(acc + b2[t], 0.f);
    __syncthreads();

    if (t < 10) {
        float o = b3[t];
        for (int k = 0; k < 128; k++) o += g[k] * __ldg(w3 + k * 10 + t);
        out[b * 10 + t] = o;
    }
}

// ---------------------------------------------------------------------------
// launch
// ---------------------------------------------------------------------------
extern "C" void kernel_launch(void* const* d_in, const int* in_sizes, int n_in,
                              void* d_out, int out_size)
{
    (void)in_sizes; (void)n_in; (void)out_size;
    const float* node_features = (const float*)d_in[0];
    const float* edge_attr     = (const float*)d_in[1];
    const float* w_msg         = (const float*)d_in[2];
    const float* b_msg         = (const float*)d_in[3];
    const float* w_self        = (const float*)d_in[4];
    const float* b_self        = (const float*)d_in[5];
    const float* w1            = (const float*)d_in[6];
    const float* b1            = (const float*)d_in[7];
    const float* w2            = (const float*)d_in[8];
    const float* b2            = (const float*)d_in[9];
    const float* w3            = (const float*)d_in[10];
    const float* b3            = (const float*)d_in[11];
    float* out = (float*)d_out;

    cudaFuncSetAttribute(edge_kernel, cudaFuncAttributeMaxDynamicSharedMemorySize,
                         EDGE_SMEM_BYTES);
    cudaFuncSetAttribute(self_uv_tf32, cudaFuncAttributeMaxDynamicSharedMemorySize,
                         SU_SMEM_BYTES);

    prepack_kernel<<<42240, 256>>>(edge_attr);

    // layer-0 u,v (uv-only mode)
    self_uv_tf32<<<229, 256, SU_SMEM_BYTES>>>(node_features, nullptr, nullptr,
                                              w_msg, b_msg);

    for (int l = 0; l < 3; l++) {
        const float* wl = w_msg + (size_t)l * 384 * 128;
        edge_kernel<<<EDGE_GRID, 512, EDGE_SMEM_BYTES>>>(wl);

        const float* xin = (l == 0) ? node_features : nullptr;
        const float* wn  = (l < 2) ? w_msg + (size_t)(l + 1) * 384 * 128 : nullptr;
        const float* bn  = (l < 2) ? b_msg + (size_t)(l + 1) * 128 : nullptr;
        self_uv_tf32<<<229, 256, SU_SMEM_BYTES>>>(xin, w_self + (size_t)l * 128 * 128,
                                                  b_self + (size_t)l * 128, wn, bn);
    }
    head_kernel<<<16, 128>>>(w1, b1, w2, b2, w3, b3, out);
}

// round 13
// speedup vs baseline: 9.8710x; 1.0202x over previous
#include <cuda_runtime.h>
#include <cuda_bf16.h>
#include <cstdint>
#include <cstddef>

#define BB 16
#define NN 458
#define DD 128
#define EE 42240
#define NROWS (BB * NN)
#define AGG_STRIDE (BB * NN * DD)
#define N_ITEMS 672
#define EDGE_GRID 148

// ---------------------------------------------------------------------------
// Scratch (device globals)
// ---------------------------------------------------------------------------
__device__ float g_x  [BB * NN * DD];
__device__ float g_u  [BB * NN * DD];
__device__ float g_v  [BB * NN * DD];
__device__ float g_agg[8 * BB * NN * DD];
__device__ uint4 g_ebf[BB * EE * 16];            // edge_attr bf16x2 packed
__device__ __align__(16) float g_wtf[9 * 17408]; // node W tf32(RNA), padded 136

// ---------------------------------------------------------------------------
// helpers
// ---------------------------------------------------------------------------
__device__ __forceinline__ uint32_t packbf(float lo, float hi) {
    uint32_t r;
    asm("cvt.rn.bf16x2.f32 %0, %1, %2;" : "=r"(r) : "f"(hi), "f"(lo));
    return r;
}
__device__ __forceinline__ float to_tf32(float x) {
    uint32_t u;
    asm("cvt.rna.tf32.f32 %0, %1;" : "=r"(u) : "f"(x));
    return __uint_as_float(u);
}
__device__ __forceinline__ uint32_t smem_u32(const void* p) {
    uint32_t a;
    asm("{ .reg .u64 t; cvta.to.shared.u64 t, %1; cvt.u32.u64 %0, t; }"
        : "=r"(a) : "l"(p));
    return a;
}
__device__ __forceinline__ void mma16(float& c0, float& c1, float& c2, float& c3,
                                      uint32_t a0, uint32_t a1, uint32_t a2, uint32_t a3,
                                      uint32_t b0, uint32_t b1) {
    asm volatile(
        "mma.sync.aligned.m16n8k16.row.col.f32.bf16.bf16.f32 "
        "{%0,%1,%2,%3},{%4,%5,%6,%7},{%8,%9},{%0,%1,%2,%3};"
        : "+f"(c0), "+f"(c1), "+f"(c2), "+f"(c3)
        : "r"(a0), "r"(a1), "r"(a2), "r"(a3), "r"(b0), "r"(b1));
}
__device__ __forceinline__ void mma8(float& c0, float& c1, float& c2, float& c3,
                                     uint32_t a0, uint32_t a1, uint32_t a2, uint32_t a3,
                                     uint32_t b0, uint32_t b1) {
    asm volatile(
        "mma.sync.aligned.m16n8k8.row.col.f32.tf32.tf32.f32 "
        "{%0,%1,%2,%3},{%4,%5,%6,%7},{%8,%9},{%0,%1,%2,%3};"
        : "+f"(c0), "+f"(c1), "+f"(c2), "+f"(c3)
        : "r"(a0), "r"(a1), "r"(a2), "r"(a3), "r"(b0), "r"(b1));
}
__device__ __forceinline__ void ldsm_x4(uint32_t& r0, uint32_t& r1, uint32_t& r2,
                                        uint32_t& r3, uint32_t addr) {
    asm volatile("ldmatrix.sync.aligned.m8n8.x4.shared.b16 {%0,%1,%2,%3}, [%4];"
                 : "=r"(r0), "=r"(r1), "=r"(r2), "=r"(r3) : "r"(addr));
}
__device__ __forceinline__ void cp16(uint32_t daddr, const void* gptr, uint32_t srcsize) {
    asm volatile("cp.async.cg.shared.global [%0], [%1], 16, %2;"
                 :: "r"(daddr), "l"(gptr), "r"(srcsize) : "memory");
}

// ---------------------------------------------------------------------------
// prepack kernels
// ---------------------------------------------------------------------------
__global__ __launch_bounds__(256) void prepack_kernel(const float* __restrict__ ea)
{
    const size_t i = (size_t)blockIdx.x * 256 + threadIdx.x;
    const float4 f0 = *(const float4*)(ea + i * 8);
    const float4 f1 = *(const float4*)(ea + i * 8 + 4);
    g_ebf[i] = make_uint4(packbf(f0.x, f0.y), packbf(f0.z, f0.w),
                          packbf(f1.x, f1.y), packbf(f1.z, f1.w));
}

// 9 node matrices (l x {self=0, src=1, dst=2}) -> tf32 RNA, padded to 136 cols
__global__ __launch_bounds__(256) void prepack_wt(const float* __restrict__ w_self,
                                                  const float* __restrict__ w_msg)
{
    const int m = blockIdx.x, l = m / 3, k = m % 3;
    const float* src = (k == 0) ? (w_self + (size_t)l * 16384)
                                : (w_msg + (size_t)l * 49152 + (size_t)(k - 1) * 16384);
    float* out = g_wtf + (size_t)m * 17408;
    for (int i = threadIdx.x; i < 17408; i += 256) {
        const int kr = i / 136, c = i % 136;
        out[i] = (c < 128) ? to_tf32(src[kr * 128 + c]) : 0.f;
    }
}

// ---------------------------------------------------------------------------
// persistent edge kernel (unchanged from R10 best): 148 CTAs, 512 threads
// ---------------------------------------------------------------------------
#define EW_SW 0
#define EW_SA 8704
#define EW_SV (EW_SA + 3 * 4352)
#define EW_SU (EW_SV + 64 * 132)
#define EDGE_SMEM_WORDS (EW_SU + 3 * 512)
#define EDGE_SMEM_BYTES (EDGE_SMEM_WORDS * 4)

__global__ __launch_bounds__(512, 1) void edge_kernel(const float* __restrict__ wl)
{
    extern __shared__ uint32_t smw[];
    uint32_t* sWp = smw + EW_SW;
    float* sV = (float*)(smw + EW_SV);
    float* sU = (float*)(smw + EW_SU);
    const uint32_t sb = smem_u32(smw);
    const int tid = threadIdx.x;

    {
        const float* wedge = wl + 256 * 128;
        for (int i = tid; i < 8192; i += 512) {
            const int kp = i >> 7, n = i & 127;
            sWp[kp * 136 + n] = packbf(wedge[(2 * kp) * 128 + n],
                                       wedge[(2 * kp + 1) * 128 + n]);
        }
    }
    __syncthreads();

    const int w    = tid >> 5;
    const int lane = tid & 31;
    const int wm   = w & 3;
    const int wn   = w >> 2;
    const int g    = lane >> 2;
    const int tig  = lane & 3;

    uint32_t bB[8][4][2];
    #pragma unroll
    for (int ks = 0; ks < 8; ks++)
        #pragma unroll
        for (int nt = 0; nt < 4; nt++) {
            const int n = wn * 32 + nt * 8 + g;
            bB[ks][nt][0] = sWp[(ks * 8 + tig) * 136 + n];
            bB[ks][nt][1] = sWp[(ks * 8 + tig + 4) * 136 + n];
        }

    const int quad  = lane >> 3;
    const int r8    = lane & 7;
    const int rowL  = wm * 16 + (quad & 1) * 8 + r8;
    const int koffL = (quad >> 1) * 4;
    const uint32_t aAddr0 = sb + (EW_SA + rowL * 68 + koffL) * 4u;

    const int nsrc_a[4] = {64, 128, 128, 128};
    const int ndst_a[4] = {128, 128, 128, 10};
    const int eb_a  [4] = {0, 8192, 24576, 40960};
    const int so_a  [4] = {0, 64, 192, 320};
    const int do_a  [4] = {64, 192, 320, 448};

    for (int item = blockIdx.x; item < N_ITEMS; item += EDGE_GRID) {
        const int b = item / 42, r = item % 42;
        int lb, dtile, chunk, s_begin;
        if (r < 8)       { lb = 0; dtile = r >> 2;          chunk = r & 3;  s_begin = chunk * 16; }
        else if (r < 24) { lb = 1; const int q = r - 8;  dtile = q & 1; chunk = q >> 1; s_begin = chunk * 16; }
        else if (r < 40) { lb = 2; const int q = r - 24; dtile = q & 1; chunk = q >> 1; s_begin = chunk * 16; }
        else             { lb = 3; const int q = r - 40; dtile = 0;     chunk = q * 4;  s_begin = q * 64; }

        const int n_src = nsrc_a[lb];
        const int n_dst = ndst_a[lb];
        const int ebase = eb_a[lb];
        const int soff  = so_a[lb];
        const int doff  = do_a[lb];
        const int d0    = dtile * 64;
        const bool packed4 = (lb == 3);
        const int sshift = packed4 ? 4 : 6;
        const int rmask  = packed4 ? 15 : 63;
        const int sstep  = packed4 ? 4 : 1;
        const int nsrow  = packed4 ? 4 : 1;

        auto stageA = [&](int buf, int i) {
            const uint32_t dbase = sb + (EW_SA + buf * 4352) * 4;
            const int s0 = s_begin + i * sstep;
            #pragma unroll
            for (int j = 0; j < 2; j++) {
                const int idx = tid + 512 * j;
                const int row = idx >> 4, c = idx & 15;
                const int dgl = row & rmask;
                const int s   = s0 + (row >> sshift);
                const bool ok = (d0 + dgl < n_dst);
                const size_t e = (size_t)b * EE + ebase +
                                 (ok ? ((size_t)s * n_dst + d0 + dgl) : 0);
                cp16(dbase + (uint32_t)(row * 68 + c * 4) * 4u,
                     g_ebf + e * 16 + c, ok ? 16u : 0u);
            }
        };
        auto stageU = [&](int slot, int i) {
            if (tid < 32 * nsrow) {
                const int sl = tid >> 5, c4 = tid & 31;
                cp16(sb + (EW_SU + slot * 512 + sl * 128 + c4 * 4) * 4u,
                     g_u + ((size_t)b * NN + soff + s_begin + i * sstep + sl) * DD + c4 * 4,
                     16u);
            }
        };

        stageA(0, 0); stageU(0, 0);
        asm volatile("cp.async.commit_group;" ::: "memory");
        stageA(1, 1); stageU(1, 1);
        asm volatile("cp.async.commit_group;" ::: "memory");

        for (int i = tid; i < 2048; i += 512) {
            const int row = i >> 5, c4 = i & 31;
            const int dgl = row & rmask;
            float4 v4 = make_float4(0.f, 0.f, 0.f, 0.f);
            if (d0 + dgl < n_dst)
                v4 = *(const float4*)(g_v + ((size_t)b * NN + doff + d0 + dgl) * DD + c4 * 4);
            *(float4*)(sV + row * 132 + c4 * 4) = v4;
        }
        asm volatile("cp.async.wait_group 1;" ::: "memory");
        __syncthreads();

        float agg[4][4];
        #pragma unroll
        for (int nt = 0; nt < 4; nt++)
            #pragma unroll
            for (int rr = 0; rr < 4; rr++) agg[nt][rr] = 0.f;

        for (int i = 0; i < 16; i++) {
            const int p = i % 3;
            if (i + 2 < 16) {
                stageA((i + 2) % 3, i + 2);
                stageU((i + 2) % 3, i + 2);
            }
            asm volatile("cp.async.commit_group;" ::: "memory");

            float acc[4][4];
            #pragma unroll
            for (int nt = 0; nt < 4; nt++)
                #pragma unroll
                for (int rr = 0; rr < 4; rr++) acc[nt][rr] = 0.f;

            const uint32_t aBase = aAddr0 + (uint32_t)p * (4352u * 4u);
            #pragma unroll
            for (int ks = 0; ks < 8; ks++) {
                uint32_t a0, a1, a2, a3;
                ldsm_x4(a0, a1, a2, a3, aBase + (uint32_t)ks * 32u);
                #pragma unroll
                for (int nt = 0; nt < 4; nt++)
                    mma16(acc[nt][0], acc[nt][1], acc[nt][2], acc[nt][3],
                          a0, a1, a2, a3, bB[ks][nt][0], bB[ks][nt][1]);
            }

            const float* sUp = sU + p * 512 + (packed4 ? wm * 128 : 0);
            const int r0 = wm * 16 + g;
            #pragma unroll
            for (int nt = 0; nt < 4; nt++) {
                const int col = wn * 32 + nt * 8 + 2 * tig;
                const float2 uu = *(const float2*)(sUp + col);
                const float2 v0 = *(const float2*)(sV + r0 * 132 + col);
                const float2 v1 = *(const float2*)(sV + (r0 + 8) * 132 + col);
                agg[nt][0] += fmaxf(acc[nt][0] + uu.x + v0.x, 0.f);
                agg[nt][1] += fmaxf(acc[nt][1] + uu.y + v0.y, 0.f);
                agg[nt][2] += fmaxf(acc[nt][2] + uu.x + v1.x, 0.f);
                agg[nt][3] += fmaxf(acc[nt][3] + uu.y + v1.y, 0.f);
            }

            asm volatile("cp.async.wait_group 1;" ::: "memory");
            __syncthreads();
        }

        const float scale = 1.f / (float)n_src;
        const int chunkbuf = packed4 ? (chunk + wm) : chunk;
        float* aggbuf = g_agg + (size_t)chunkbuf * AGG_STRIDE;
        const int dg0 = d0 + ((wm * 16 + g) & rmask);
        const int dg1 = d0 + ((wm * 16 + g + 8) & rmask);
        #pragma unroll
        for (int nt = 0; nt < 4; nt++) {
            const int col = wn * 32 + nt * 8 + 2 * tig;
            if (dg0 < n_dst)
                *(float2*)(aggbuf + ((size_t)b * NN + doff + dg0) * DD + col) =
                    make_float2(agg[nt][0] * scale, agg[nt][1] * scale);
            if (dg1 < n_dst)
                *(float2*)(aggbuf + ((size_t)b * NN + doff + dg1) * DD + col) =
                    make_float2(agg[nt][2] * scale, agg[nt][3] * scale);
        }
        __syncthreads();
    }
}

// ---------------------------------------------------------------------------
// self_uv_tf32: 64-row tiles, 115 CTAs, 512 threads, tf32 mma, prepacked W.
//
// W-buffer contract (explicit, both modes):
//   self mode  (m0>=0): G0 = Wself->W0, G1 = Wsrc->W1, G2(after gemm1) = Wdst->W0
//                       gemm1 reads W0; gemm2 reads W1; gemm3 reads W0.
//   uv-only    (m0<0):  G0 = Wsrc->W0,  G1 = Wdst->W1
//                       gemm2 reads W0; gemm3 reads W1.
// ---------------------------------------------------------------------------
#define SV_W0 0
#define SV_W1 17408
#define SV_XS 34816
#define SV_XN 43264
#define SV_WORDS 51712
#define SV_SMEM_BYTES (SV_WORDS * 4)

__global__ __launch_bounds__(512, 1) void self_uv_tf32(const float* __restrict__ xin,
                                                       int m0,
                                                       const float* __restrict__ bself,
                                                       int msrc,
                                                       const float* __restrict__ bnext)
{
    extern __shared__ float smf[];
    float* W0 = smf + SV_W0;
    float* W1 = smf + SV_W1;
    float* xs = smf + SV_XS;
    float* xn = smf + SV_XN;
    const uint32_t sb = smem_u32(smf);

    const int tid  = threadIdx.x;
    const int row0 = blockIdx.x * 64;
    const float* x = (xin != nullptr) ? xin : g_x;
    const bool selfmode = (m0 >= 0);
    const bool have_uv  = (msrc >= 0);

    auto stageW = [&](int wbuf, int m) {
        const uint32_t dbase = sb + (wbuf ? SV_W1 : SV_W0) * 4u;
        const float* src = g_wtf + (size_t)m * 17408;
        #pragma unroll
        for (int j = 0; j < 9; j++) {
            const int i = tid + 512 * j;
            if (i < 4352) cp16(dbase + (uint32_t)i * 16u, src + i * 4, 16u);
        }
    };

    // G0
    stageW(0, selfmode ? m0 : msrc);
    asm volatile("cp.async.commit_group;" ::: "memory");
    // G1
    if (have_uv) stageW(1, selfmode ? msrc : (msrc + 1));
    asm volatile("cp.async.commit_group;" ::: "memory");

    // stage x (tf32) into xs (self mode) or xn (uv-only)
    {
        float* xt = selfmode ? xs : xn;
        for (int i = tid; i < 2048; i += 512) {
            const int rr = i >> 5, c4 = i & 31;
            const int row = row0 + rr;
            float4 xv = make_float4(0.f, 0.f, 0.f, 0.f);
            if (row < NROWS)
                xv = *(const float4*)(x + (size_t)row * DD + c4 * 4);
            xv.x = to_tf32(xv.x); xv.y = to_tf32(xv.y);
            xv.z = to_tf32(xv.z); xv.w = to_tf32(xv.w);
            *(float4*)(xt + rr * 132 + c4 * 4) = xv;
        }
    }
    asm volatile("cp.async.wait_group 1;" ::: "memory");   // G0 complete
    __syncthreads();

    const int w    = tid >> 5;
    const int lane = tid & 31;
    const int wm   = w & 3;
    const int wn   = w >> 2;
    const int g    = lane >> 2;
    const int tig  = lane & 3;
    const int rowg0 = row0 + wm * 16 + g;

    auto gemm = [&](const float* A, const float* W, float (&acc)[4][4]) {
        #pragma unroll
        for (int nt = 0; nt < 4; nt++)
            #pragma unroll
            for (int rr = 0; rr < 4; rr++) acc[nt][rr] = 0.f;
        const uint32_t* Au = (const uint32_t*)A;
        const uint32_t* Wu = (const uint32_t*)W;
        const int base0 = (wm * 16 + g) * 132;
        #pragma unroll
        for (int ks = 0; ks < 16; ks++) {
            const int kb = ks * 8;
            const uint32_t a0 = Au[base0 + kb + tig];
            const uint32_t a1 = Au[base0 + 8 * 132 + kb + tig];
            const uint32_t a2 = Au[base0 + kb + tig + 4];
            const uint32_t a3 = Au[base0 + 8 * 132 + kb + tig + 4];
            #pragma unroll
            for (int nt = 0; nt < 4; nt++) {
                const int n = wn * 32 + nt * 8 + g;
                const uint32_t b0 = Wu[(kb + tig) * 136 + n];
                const uint32_t b1 = Wu[(kb + tig + 4) * 136 + n];
                mma8(acc[nt][0], acc[nt][1], acc[nt][2], acc[nt][3],
                     a0, a1, a2, a3, b0, b1);
            }
        }
    };

    if (selfmode) {
        // gemm1: x @ Wself (W0)
        float acc[4][4];
        gemm(xs, W0, acc);

        #pragma unroll
        for (int rr = 0; rr < 2; rr++) {
            const int row = rowg0 + rr * 8;
            const bool valid = (row < NROWS);
            const int nodeidx = row % NN;
            const bool hasagg = valid && (nodeidx >= 64);
            const int nbuf = (nodeidx < 192) ? 4 : 8;
            #pragma unroll
            for (int nt = 0; nt < 4; nt++) {
                const int col = wn * 32 + nt * 8 + 2 * tig;
                float c0 = acc[nt][rr * 2 + 0] + __ldg(bself + col);
                float c1 = acc[nt][rr * 2 + 1] + __ldg(bself + col + 1);
                if (hasagg) {
                    const size_t o = (size_t)row * DD + col;
                    for (int cb = 0; cb < nbuf; cb++) {
                        const float2 av = *(const float2*)(g_agg + (size_t)cb * AGG_STRIDE + o);
                        c0 += av.x; c1 += av.y;
                    }
                }
                c0 = fmaxf(c0, 0.f);
                c1 = fmaxf(c1, 0.f);
                if (valid)
                    *(float2*)(g_x + (size_t)row * DD + col) = make_float2(c0, c1);
                *(float2*)(xn + (wm * 16 + g + rr * 8) * 132 + col) =
                    make_float2(to_tf32(c0), to_tf32(c1));
            }
        }
        __syncthreads();   // xn complete; all warps past W0 reads
        // G2: Wdst -> W0 (overlaps gemm2)
        if (have_uv) {
            stageW(0, msrc + 1);
            asm volatile("cp.async.commit_group;" ::: "memory");
        }
    }

    if (have_uv) {
        // gemm2: u = xn @ Wsrc.  Wsrc is W1 in self mode, W0 in uv-only mode.
        asm volatile("cp.async.wait_group 1;" ::: "memory");   // G1 complete
        {
            float acc[4][4];
            gemm(xn, selfmode ? W1 : W0, acc);
            #pragma unroll
            for (int rr = 0; rr < 2; rr++) {
                const int row = rowg0 + rr * 8;
                if (row < NROWS) {
                    #pragma unroll
                    for (int nt = 0; nt < 4; nt++) {
                        const int col = wn * 32 + nt * 8 + 2 * tig;
                        *(float2*)(g_u + (size_t)row * DD + col) =
                            make_float2(acc[nt][rr * 2 + 0], acc[nt][rr * 2 + 1]);
                    }
                }
            }
        }
        // gemm3: v = xn @ Wdst + bias.  Wdst is W0 (self mode, G2) or W1 (uv-only).
        asm volatile("cp.async.wait_group 0;" ::: "memory");
        __syncthreads();
        {
            float acc[4][4];
            gemm(xn, selfmode ? W0 : W1, acc);
            #pragma unroll
            for (int rr = 0; rr < 2; rr++) {
                const int row = rowg0 + rr * 8;
                if (row < NROWS) {
                    #pragma unroll
                    for (int nt = 0; nt < 4; nt++) {
                        const int col = wn * 32 + nt * 8 + 2 * tig;
                        *(float2*)(g_v + (size_t)row * DD + col) =
                            make_float2(acc[nt][rr * 2 + 0] + __ldg(bnext + col),
                                        acc[nt][rr * 2 + 1] + __ldg(bnext + col + 1));
                    }
                }
            }
        }
    }
}

// ---------------------------------------------------------------------------
// head kernel
// ---------------------------------------------------------------------------
__global__ __launch_bounds__(128) void head_kernel(const float* __restrict__ w1,
                                                   const float* __restrict__ b1,
                                                   const float* __restrict__ w2,
                                                   const float* __restrict__ b2,
                                                   const float* __restrict__ w3,
                                                   const float* __restrict__ b3,
                                                   float* __restrict__ out)
{
    __shared__ float g[128];
    __shared__ float h[128];
    const int b = blockIdx.x;
    const int t = threadIdx.x;

    float s = 0.f;
    const float* xb = g_x + (size_t)b * NN * DD;
    for (int n = 0; n < NN; n++) s += xb[(size_t)n * DD + t];
    g[t] = s * (1.f / (float)NN);
    __syncthreads();

    float acc = 0.f;
    #pragma unroll 4
    for (int k = 0; k < 128; k++) acc += g[k] * __ldg(w1 + k * 128 + t);
    h[t] = fmaxf(acc + b1[t], 0.f);
    __syncthreads();

    acc = 0.f;
    #pragma unroll 4
    for (int k = 0; k < 128; k++) acc += h[k] * __ldg(w2 + k * 128 + t);
    __syncthreads();
    g[t] = fmaxf(acc + b2[t], 0.f);
    __syncthreads();

    if (t < 10) {
        float o = b3[t];
        for (int k = 0; k < 128; k++) o += g[k] * __ldg(w3 + k * 10 + t);
        out[b * 10 + t] = o;
    }
}

// ---------------------------------------------------------------------------
// launch
// ---------------------------------------------------------------------------
extern "C" void kernel_launch(void* const* d_in, const int* in_sizes, int n_in,
                              void* d_out, int out_size)
{
    (void)in_sizes; (void)n_in; (void)out_size;
    const float* node_features = (const float*)d_in[0];
    const float* edge_attr     = (const float*)d_in[1];
    const float* w_msg         = (const float*)d_in[2];
    const float* b_msg         = (const float*)d_in[3];
    const float* w_self        = (const float*)d_in[4];
    const float* b_self        = (const float*)d_in[5];
    const float* w1            = (const float*)d_in[6];
    const float* b1            = (const float*)d_in[7];
    const float* w2            = (const float*)d_in[8];
    const float* b2            = (const float*)d_in[9];
    const float* w3            = (const float*)d_in[10];
    const float* b3            = (const float*)d_in[11];
    float* out = (float*)d_out;

    cudaFuncSetAttribute(edge_kernel, cudaFuncAttributeMaxDynamicSharedMemorySize,
                         EDGE_SMEM_BYTES);
    cudaFuncSetAttribute(self_uv_tf32, cudaFuncAttributeMaxDynamicSharedMemorySize,
                         SV_SMEM_BYTES);

    prepack_kernel<<<42240, 256>>>(edge_attr);
    prepack_wt<<<9, 256>>>(w_self, w_msg);

    // layer-0: uv-only mode (m0 = -1, msrc = matrix idx of layer-0 Wsrc = 1)
    self_uv_tf32<<<115, 512, SV_SMEM_BYTES>>>(node_features, -1, nullptr, 1, b_msg);

    for (int l = 0; l < 3; l++) {
        const float* wl = w_msg + (size_t)l * 384 * 128;
        edge_kernel<<<EDGE_GRID, 512, EDGE_SMEM_BYTES>>>(wl);

        const float* xin = (l == 0) ? node_features : nullptr;
        const int msrc = (l < 2) ? (3 * (l + 1) + 1) : -1;
        const float* bn = (l < 2) ? (b_msg + (size_t)(l + 1) * 128) : nullptr;
        self_uv_tf32<<<115, 512, SV_SMEM_BYTES>>>(xin, 3 * l,
                                                  b_self + (size_t)l * 128, msrc, bn);
    }
    head_kernel<<<16, 128>>>(w1, b1, w2, b2, w3, b3, out);
}